// round 6
// baseline (speedup 1.0000x reference)
#include <cuda_runtime.h>
#include <math.h>

// ---------------- problem constants ----------------
#define NN    4096
#define KNNK  20
#define LRKK  40
#define EPN   60          // edges per node (20 knn + 40 lr)
#define LL    9           // (LMAX+1)^2
#define SPH   35          // BBC + NBB
#define BBC   32
#define NBB   3
#define HEADS 8
#define HV    64          // HEADS * VC
#define HC    32
#define AIN   102         // 2*SPH + 32 edge features
#define EPB   64          // edges per block in edge kernel

#define OFF_BB  (NN*3)
#define OFF_OUT (NN*3 + NN*9)

// ---------------- scratch (static device globals; no runtime alloc) ----------
__device__ int   g_src[NN*EPN];
__device__ float g_logit[NN*EPN*HEADS];
__device__ float g_inv[NN*SPH];
__device__ float g_v[NN*LL*HV];

__constant__ int c_L3[LL] = {0,1,1,1,2,2,2,2,2};

// ---------------- threefry2x32 gumbel (JAX partitionable path) --------------
// key = jax.random.key(1) -> (k1,k2) = (0,1); counter lo = element index
// bits = out0 ^ out1; u = bitcast((bits>>9)|0x3f800000)-1; u = max(u, tiny);
// g = -log(-log(u))
__device__ __forceinline__ float gumbel32(unsigned int idx) {
    unsigned int x0 = 0u, x1 = idx;
    const unsigned int ks0 = 0u, ks1 = 1u, ks2 = 0x1BD11BDBu; // 0x1BD11BDA ^ 0 ^ 1
    x0 += ks0; x1 += ks1;
#define TFR(r) { x0 += x1; x1 = __funnelshift_l(x1, x1, (r)); x1 ^= x0; }
    TFR(13) TFR(15) TFR(26) TFR(6);  x0 += ks1; x1 += ks2 + 1u;
    TFR(17) TFR(29) TFR(16) TFR(24); x0 += ks2; x1 += ks0 + 2u;
    TFR(13) TFR(15) TFR(26) TFR(6);  x0 += ks0; x1 += ks1 + 3u;
    TFR(17) TFR(29) TFR(16) TFR(24); x0 += ks1; x1 += ks2 + 4u;
    TFR(13) TFR(15) TFR(26) TFR(6);  x0 += ks2; x1 += ks0 + 5u;
#undef TFR
    unsigned int bits = x0 ^ x1;
    float u = __uint_as_float((bits >> 9) | 0x3f800000u) - 1.0f;
    u = fmaxf(u, 1.17549435e-38f);
    return -logf(-logf(u));
}

// ---------------- kernel 1: node features + V = so3_linear(node, wv, bv) ----
__global__ __launch_bounds__(64) void node_v_kernel(
    const float* __restrict__ bbf, const float* __restrict__ bbr,
    const int* __restrict__ noise,
    const float* __restrict__ wv, const float* __restrict__ bv)
{
    __shared__ float nf[LL*SPH];
    const int i = blockIdx.x;
    const int t = threadIdx.x;
    for (int idx = t; idx < LL*SPH; idx += 64) {
        int l = idx / SPH, c = idx - l*SPH;
        float v = 0.f;
        if (c < BBC)                    v = bbf[(i*LL + l)*BBC + c];
        else if (l >= 1 && l <= 3)      v = bbr[(i*NBB + (c-BBC))*3 + (l-1)];
        if (l == 0 && c == SPH-1)       v = noise[i] ? 1.0f : 0.0f;
        nf[idx] = v;
    }
    __syncthreads();
    if (t < SPH) g_inv[i*SPH + t] = nf[t];
    const int d = t;  // 0..63
#pragma unroll
    for (int l = 0; l < LL; ++l) {
        const float* w = wv + c_L3[l]*SPH*HV;
        float acc = 0.f;
#pragma unroll 7
        for (int c = 0; c < SPH; ++c) acc = __fmaf_rn(nf[l*SPH + c], w[c*HV + d], acc);
        if (l == 0) acc += bv[d];
        g_v[(i*LL + l)*HV + d] = acc;
    }
}

// ---------------- kernel 2: per-row distances + knn top20 + gumbel top40 ----
__global__ __launch_bounds__(256) void row_kernel(
    const float* __restrict__ X, const int* __restrict__ batch,
    const int* __restrict__ xmask)
{
    __shared__ float s_key[NN];
    __shared__ float s_lg[NN];
    __shared__ float s_rv[8];
    __shared__ int   s_ri[8];
    const int i = blockIdx.x;
    const int t = threadIdx.x;
    const int lane = t & 31, warp = t >> 5;

    const float xi = X[3*i+0], yi = X[3*i+1], zi = X[3*i+2];
    // x2 = sum(X*X): elementwise square then reduce (mul + add, no FMA)
    const float x2i = __fadd_rn(__fadd_rn(__fmul_rn(xi,xi),__fmul_rn(yi,yi)),__fmul_rn(zi,zi));
    const int bi = batch[i];
    const int mi = xmask[i];

    for (int j = t; j < NN; j += 256) {
        float xj = X[3*j+0], yj = X[3*j+1], zj = X[3*j+2];
        float x2j = __fadd_rn(__fadd_rn(__fmul_rn(xj,xj),__fmul_rn(yj,yj)),__fmul_rn(zj,zj));
        // X @ X.T: exact fp32 sgemm, sequential FMA over K
        float dot = __fmul_rn(xi, xj);
        dot = __fmaf_rn(yi, yj, dot);
        dot = __fmaf_rn(zi, zj, dot);
        float d2  = fmaxf(__fsub_rn(__fadd_rn(x2i,x2j), __fmul_rn(2.0f,dot)), 0.0f);
        bool invalid = (batch[j] != bi) || (j == i) || (mi != 0) || (xmask[j] != 0);
        s_key[j] = invalid ? 1e30f : d2;
    }
    __syncthreads();

    // ---- 20 iterative argmins (tie-break lowest index, JAX top_k semantics)
    for (int it = 0; it < KNNK; ++it) {
        float bvv = 3.4e38f; int bii = NN;
        for (int j = t; j < NN; j += 256) {
            float v = s_key[j];
            if (v < bvv) { bvv = v; bii = j; }
        }
#pragma unroll
        for (int off = 16; off; off >>= 1) {
            float ov = __shfl_xor_sync(0xffffffffu, bvv, off);
            int   oi = __shfl_xor_sync(0xffffffffu, bii, off);
            if (ov < bvv || (ov == bvv && oi < bii)) { bvv = ov; bii = oi; }
        }
        if (lane == 0) { s_rv[warp] = bvv; s_ri[warp] = bii; }
        __syncthreads();
        if (t == 0) {
            float bv2 = s_rv[0]; int bi2 = s_ri[0];
            for (int w = 1; w < 8; ++w)
                if (s_rv[w] < bv2 || (s_rv[w] == bv2 && s_ri[w] < bi2)) { bv2 = s_rv[w]; bi2 = s_ri[w]; }
            g_src[i*EPN + it] = bi2;
            s_key[bi2] = 3.0e38f;  // exclude; also marks knn membership
        }
        __syncthreads();
    }

    // ---- logits + gumbel for valid non-knn entries
    for (int j = t; j < NN; j += 256) {
        float k = s_key[j];
        float lg;
        if (k >= 5e29f) lg = -1e30f;   // invalid or knn: -BIG (gumbel absorbed in fp32)
        else {
            float g = gumbel32((unsigned)(i*NN + j));
            lg = __fadd_rn(__fmul_rn(-1.5f, logf(__fadd_rn(k, 1e-6f))), g);
        }
        s_lg[j] = lg;
    }
    __syncthreads();

    // ---- 40 iterative argmaxes
    for (int it = 0; it < LRKK; ++it) {
        float bvv = -3.4e38f; int bii = NN;
        for (int j = t; j < NN; j += 256) {
            float v = s_lg[j];
            if (v > bvv) { bvv = v; bii = j; }
        }
#pragma unroll
        for (int off = 16; off; off >>= 1) {
            float ov = __shfl_xor_sync(0xffffffffu, bvv, off);
            int   oi = __shfl_xor_sync(0xffffffffu, bii, off);
            if (ov > bvv || (ov == bvv && oi < bii)) { bvv = ov; bii = oi; }
        }
        if (lane == 0) { s_rv[warp] = bvv; s_ri[warp] = bii; }
        __syncthreads();
        if (t == 0) {
            float bv2 = s_rv[0]; int bi2 = s_ri[0];
            for (int w = 1; w < 8; ++w)
                if (s_rv[w] > bv2 || (s_rv[w] == bv2 && s_ri[w] < bi2)) { bv2 = s_rv[w]; bi2 = s_ri[w]; }
            g_src[i*EPN + KNNK + it] = bi2;
            s_lg[bi2] = -3.4e38f;
        }
        __syncthreads();
    }
}

// ---------------- kernel 3: edge MLP -> logits (1 warp per edge) -----------
__global__ __launch_bounds__(256) void edge_kernel(
    const float* __restrict__ X,
    const float* __restrict__ w1, const float* __restrict__ b1,
    const float* __restrict__ w2, const float* __restrict__ b2)
{
    __shared__ float sW1[AIN*HC];
    __shared__ float sW2[HC*HEADS];
    __shared__ float sB1[HC];
    __shared__ float sB2[HEADS];
    __shared__ float sA[8][AIN+2];
    const int t = threadIdx.x, lane = t & 31, warp = t >> 5;
    for (int idx = t; idx < AIN*HC; idx += 256) sW1[idx] = w1[idx];
    for (int idx = t; idx < HC*HEADS; idx += 256) sW2[idx] = w2[idx];
    if (t < HC)    sB1[t] = b1[t];
    if (t < HEADS) sB2[t] = b2[t];
    __syncthreads();

    const int e0 = blockIdx.x*EPB + warp*(EPB/8);
    float* a = sA[warp];
    for (int r = 0; r < EPB/8; ++r) {
        const int e = e0 + r;
        const int i = e / EPN;
        const int s = g_src[e];
        for (int c = lane; c < SPH; c += 32) {
            a[c]       = g_inv[s*SPH + c];
            a[SPH + c] = g_inv[i*SPH + c];
        }
        float dx = X[3*s+0]-X[3*i+0], dy = X[3*s+1]-X[3*i+1], dz = X[3*s+2]-X[3*i+2];
        float dist = sqrtf(__fadd_rn(__fadd_rn(__fmul_rn(dx,dx),__fmul_rn(dy,dy)),__fmul_rn(dz,dz)));
        if (lane < 16) {
            float mu = (float)lane * (20.0f/15.0f);
            float zz = (dist - mu) / 1.25f;
            a[2*SPH + lane] = expf(-zz*zz);
        }
        if (lane < 8) {
            float fr = expf((float)(2*lane) * -0.5756462732485114f);
            float ang = (float)(s - i) * fr;
            a[2*SPH + 16 + lane] = cosf(ang);
            a[2*SPH + 24 + lane] = sinf(ang);
        }
        __syncwarp();
        float h = sB1[lane];
#pragma unroll 6
        for (int c = 0; c < AIN; ++c) h = __fmaf_rn(a[c], sW1[c*HC + lane], h);
        h = h * (1.0f / (1.0f + expf(-h)));  // silu
        float p[HEADS];
#pragma unroll
        for (int hh = 0; hh < HEADS; ++hh) p[hh] = h * sW2[lane*HEADS + hh];
#pragma unroll
        for (int off = 16; off; off >>= 1)
#pragma unroll
            for (int hh = 0; hh < HEADS; ++hh)
                p[hh] += __shfl_xor_sync(0xffffffffu, p[hh], off);
        if (lane == 0) {
#pragma unroll
            for (int hh = 0; hh < HEADS; ++hh) g_logit[e*HEADS + hh] = p[hh] + sB2[hh];
        }
        __syncwarp();
    }
}

// ---------------- kernel 4: softmax + aggregate + epilogues -----------------
__global__ __launch_bounds__(64) void agg_kernel(
    const float* __restrict__ X, const float* __restrict__ bbr,
    const int* __restrict__ noise,
    const float* __restrict__ wo,   const float* __restrict__ bo,
    const float* __restrict__ wg,   const float* __restrict__ bg,
    const float* __restrict__ wf,   const float* __restrict__ bf,
    const float* __restrict__ wxca,
    const float* __restrict__ wgate, const float* __restrict__ bgate,
    const float* __restrict__ wbb,
    float* __restrict__ out)
{
    __shared__ float sal[EPN*HEADS];
    __shared__ int   ssrc[EPN];
    __shared__ float sagg[LL*HV];
    __shared__ float sout0[LL*BBC];
    __shared__ float soutf[LL*BBC];
    __shared__ float sgate[BBC];
    __shared__ float svec[3];
    __shared__ float sg2;
    __shared__ float subb[9];
    const int i = blockIdx.x;
    const int t = threadIdx.x;

    for (int idx = t; idx < EPN*HEADS; idx += 64) sal[idx] = g_logit[i*EPN*HEADS + idx];
    if (t < EPN) ssrc[t] = g_src[i*EPN + t];
    __syncthreads();

    if (t < HEADS) {
        float m = -3.4e38f;
        for (int e = 0; e < EPN; ++e) m = fmaxf(m, sal[e*HEADS + t]);
        float Z = 0.f;
        for (int e = 0; e < EPN; ++e) { float pp = expf(sal[e*HEADS+t] - m); sal[e*HEADS+t] = pp; Z += pp; }
        float inv = 1.0f / (Z + 1e-9f);
        for (int e = 0; e < EPN; ++e) sal[e*HEADS+t] *= inv;
    }
    __syncthreads();

    {
        float acc[LL];
#pragma unroll
        for (int l = 0; l < LL; ++l) acc[l] = 0.f;
        const int h = t >> 3;
        for (int e = 0; e < EPN; ++e) {
            int s = ssrc[e];
            float al = sal[e*HEADS + h];
            const float* vp = g_v + (size_t)s*LL*HV + t;
#pragma unroll
            for (int l = 0; l < LL; ++l) acc[l] = __fmaf_rn(al, vp[l*HV], acc[l]);
        }
#pragma unroll
        for (int l = 0; l < LL; ++l) sagg[l*HV + t] = acc[l];
    }
    __syncthreads();

    // out0 = so3_linear(agg, wo, bo)
    for (int idx = t; idx < LL*BBC; idx += 64) {
        int l = idx >> 5, d = idx & 31;
        const float* w = wo + c_L3[l]*HV*BBC;
        float acc = 0.f;
#pragma unroll 8
        for (int c = 0; c < HV; ++c) acc = __fmaf_rn(sagg[l*HV + c], w[c*BBC + d], acc);
        if (l == 0) acc += bo[d];
        sout0[idx] = acc;
    }
    __syncthreads();

    if (t < BBC) {
        float g = 0.f;
        for (int c = 0; c < BBC; ++c) g = __fmaf_rn(sout0[c], wg[c*BBC + t], g);
        g += bg[t];
        sgate[t] = g * (1.0f / (1.0f + expf(-g)));  // silu
    }
    __syncthreads();

    // out = out0 + so3_linear(out0, wf, bf) * gate
    for (int idx = t; idx < LL*BBC; idx += 64) {
        int l = idx >> 5, d = idx & 31;
        const float* w = wf + c_L3[l]*BBC*BBC;
        float acc = 0.f;
#pragma unroll 8
        for (int c = 0; c < BBC; ++c) acc = __fmaf_rn(sout0[l*BBC + c], w[c*BBC + d], acc);
        if (l == 0) acc += bf[d];
        float val = sout0[idx] + acc * sgate[d];
        soutf[idx] = val;
        out[OFF_OUT + (size_t)i*LL*BBC + idx] = val;
    }
    __syncthreads();

    if (t < 3) {  // vec = so3_linear(out, w_xca)[1:4,0]  (L_IDX=1, no bias at l!=0)
        float acc = 0.f;
        for (int c = 0; c < BBC; ++c) acc = __fmaf_rn(soutf[(1+t)*BBC + c], wxca[BBC + c], acc);
        svec[t] = acc;
    }
    if (t == 3) {  // g2 = softplus(out[:,0,:] @ w_gate + b_gate)
        float s = 0.f;
        for (int c = 0; c < BBC; ++c) s = __fmaf_rn(soutf[c], wgate[c], s);
        s += bgate[0];
        sg2 = fmaxf(s, 0.f) + log1pf(expf(-fabsf(s)));
    }
    if (t >= 8 && t < 17) {  // upd_bb[1+k][m], k=idx/3, m=idx%3 (L_IDX=1)
        int idx = t - 8;
        int k = idx / 3, m = idx - 3*k;
        float acc = 0.f;
        for (int c = 0; c < BBC; ++c) acc = __fmaf_rn(soutf[(1+k)*BBC + c], wbb[(BBC + c)*NBB + m], acc);
        subb[idx] = acc;
    }
    __syncthreads();

    const int nz = noise[i];
    if (t < 3)
        out[(size_t)i*3 + t] = X[i*3+t] + (nz ? svec[t]*sg2 : 0.f);
    if (t >= 8 && t < 17) {
        int idx = t - 8;
        int m = idx / 3, k = idx - 3*m;
        // dbb[m][k] = upd_bb[1+k][m] = subb[k*3+m]
        out[OFF_BB + (size_t)i*9 + idx] = bbr[(size_t)i*9 + idx] + (nz ? subb[k*3 + m] : 0.f);
    }
}

// ---------------- launch ----------------------------------------------------
extern "C" void kernel_launch(void* const* d_in, const int* in_sizes, int n_in,
                              void* d_out, int out_size)
{
    const float* X      = (const float*)d_in[0];
    const float* bbr    = (const float*)d_in[1];
    const float* bbf    = (const float*)d_in[2];
    const int*   batch  = (const int*)d_in[3];
    const int*   xmask  = (const int*)d_in[4];
    const int*   noise  = (const int*)d_in[5];
    const float* w1     = (const float*)d_in[6];
    const float* b1     = (const float*)d_in[7];
    const float* w2     = (const float*)d_in[8];
    const float* b2     = (const float*)d_in[9];
    const float* wv     = (const float*)d_in[10];
    const float* bv     = (const float*)d_in[11];
    const float* wo     = (const float*)d_in[12];
    const float* bo     = (const float*)d_in[13];
    const float* wg     = (const float*)d_in[14];
    const float* bg     = (const float*)d_in[15];
    const float* wf     = (const float*)d_in[16];
    const float* bf     = (const float*)d_in[17];
    const float* wxca   = (const float*)d_in[18];
    const float* wgate  = (const float*)d_in[20];
    const float* bgate  = (const float*)d_in[21];
    const float* wbb    = (const float*)d_in[22];
    float* out = (float*)d_out;

    node_v_kernel<<<NN, 64>>>(bbf, bbr, noise, wv, bv);
    row_kernel<<<NN, 256>>>(X, batch, xmask);
    edge_kernel<<<NN*EPN/EPB, 256>>>(X, w1, b1, w2, b2);
    agg_kernel<<<NN, 64>>>(X, bbr, noise, wo, bo, wg, bg, wf, bf,
                           wxca, wgate, bgate, wbb, out);
}

// round 7
// speedup vs baseline: 1.5572x; 1.5572x over previous
#include <cuda_runtime.h>
#include <math.h>

// ---------------- problem constants ----------------
#define NN    4096
#define KNNK  20
#define LRKK  40
#define EPN   60
#define LL    9
#define SPH   35
#define BBC   32
#define NBB   3
#define HEADS 8
#define HV    64
#define HC    32
#define AIN   102
#define EPB   64

#define OFF_BB  (NN*3)
#define OFF_OUT (NN*3 + NN*9)

__device__ int   g_src[NN*EPN];
__device__ float g_logit[NN*EPN*HEADS];
__device__ float g_inv[NN*SPH];
__device__ float g_v[NN*LL*HV];

__constant__ int c_L3[LL] = {0,1,1,1,2,2,2,2,2};

// ---------------- threefry2x32 gumbel (JAX partitionable path) --------------
__device__ __forceinline__ float gumbel32(unsigned int idx) {
    unsigned int x0 = 0u, x1 = idx;
    const unsigned int ks0 = 0u, ks1 = 1u, ks2 = 0x1BD11BDBu;
    x0 += ks0; x1 += ks1;
#define TFR(r) { x0 += x1; x1 = __funnelshift_l(x1, x1, (r)); x1 ^= x0; }
    TFR(13) TFR(15) TFR(26) TFR(6);  x0 += ks1; x1 += ks2 + 1u;
    TFR(17) TFR(29) TFR(16) TFR(24); x0 += ks2; x1 += ks0 + 2u;
    TFR(13) TFR(15) TFR(26) TFR(6);  x0 += ks0; x1 += ks1 + 3u;
    TFR(17) TFR(29) TFR(16) TFR(24); x0 += ks1; x1 += ks2 + 4u;
    TFR(13) TFR(15) TFR(26) TFR(6);  x0 += ks2; x1 += ks0 + 5u;
#undef TFR
    unsigned int bits = x0 ^ x1;
    float u = __uint_as_float((bits >> 9) | 0x3f800000u) - 1.0f;
    u = fmaxf(u, 1.17549435e-38f);
    return -logf(-logf(u));
}

// ---------------- kernel 1: node features + V ------------------------------
__global__ __launch_bounds__(64) void node_v_kernel(
    const float* __restrict__ bbf, const float* __restrict__ bbr,
    const int* __restrict__ noise,
    const float* __restrict__ wv, const float* __restrict__ bv)
{
    __shared__ float nf[LL*SPH];
    const int i = blockIdx.x;
    const int t = threadIdx.x;
    for (int idx = t; idx < LL*SPH; idx += 64) {
        int l = idx / SPH, c = idx - l*SPH;
        float v = 0.f;
        if (c < BBC)                    v = bbf[(i*LL + l)*BBC + c];
        else if (l >= 1 && l <= 3)      v = bbr[(i*NBB + (c-BBC))*3 + (l-1)];
        if (l == 0 && c == SPH-1)       v = noise[i] ? 1.0f : 0.0f;
        nf[idx] = v;
    }
    __syncthreads();
    if (t < SPH) g_inv[i*SPH + t] = nf[t];
    const int d = t;
#pragma unroll
    for (int l = 0; l < LL; ++l) {
        const float* w = wv + c_L3[l]*SPH*HV;
        float acc = 0.f;
#pragma unroll 7
        for (int c = 0; c < SPH; ++c) acc = __fmaf_rn(nf[l*SPH + c], w[c*HV + d], acc);
        if (l == 0) acc += bv[d];
        g_v[(i*LL + l)*HV + d] = acc;
    }
}

// ---------------- radix-select helpers --------------------------------------
// Find the k-th smallest key among elements with key < validMax.
// Returns (T, need): T = k-th smallest key value; need = how many ==T ties to take.
__device__ __forceinline__ uint2 radix_select_k(
    const unsigned* s_key, unsigned (*hist)[256], unsigned* sScan,
    unsigned k, unsigned validMax, int t)
{
    const int lane = t & 31, w = t >> 5;
    unsigned prefix = 0, kk = k;
#pragma unroll
    for (int byte = 3; byte >= 0; --byte) {
        const unsigned maskHi = (byte == 3) ? 0u : (0xFFFFFFFFu << (8*(byte+1)));
#pragma unroll
        for (int c = 0; c < 8; ++c) hist[c][t] = 0;
        __syncthreads();
        for (int j = t; j < NN; j += 256) {
            unsigned u = s_key[j];
            if (u < validMax && (u & maskHi) == prefix)
                atomicAdd(&hist[w][(u >> (8*byte)) & 255u], 1u);
        }
        __syncthreads();
        unsigned cnt = 0;
#pragma unroll
        for (int c = 0; c < 8; ++c) cnt += hist[c][t];
        unsigned v = cnt;
#pragma unroll
        for (int o = 1; o < 32; o <<= 1) {
            unsigned n = __shfl_up_sync(0xffffffffu, v, o);
            if (lane >= o) v += n;
        }
        if (lane == 31) sScan[w] = v;
        __syncthreads();
        if (t == 0) {
            unsigned a = 0;
#pragma unroll
            for (int c = 0; c < 8; ++c) { unsigned x = sScan[c]; sScan[c] = a; a += x; }
        }
        __syncthreads();
        unsigned incl = v + sScan[w];
        unsigned excl = incl - cnt;
        if (kk > excl && kk <= incl) { sScan[8] = (unsigned)t; sScan[9] = excl; }
        __syncthreads();
        prefix |= sScan[8] << (8*byte);
        kk -= sScan[9];
        __syncthreads();
    }
    return make_uint2(prefix, kk);
}

// Deterministic, index-ordered collection: all keys < T, then first `need`
// keys == T in ascending index order (JAX stable tie-break).
__device__ __forceinline__ void collect_k(
    const unsigned* s_key, unsigned T, int cLess, int need,
    int* sel, unsigned* sc, int t)
{
    const int lane = t & 31, w = t >> 5;
    const unsigned lm = (1u << lane) - 1u;
    int runL = 0, runE = 0;
    for (int base = 0; base < NN; base += 256) {
        const int j = base + t;
        const unsigned u = s_key[j];
        const bool pL = (u < T);
        const bool pE = (u == T);
        unsigned balL = __ballot_sync(0xffffffffu, pL);
        unsigned balE = __ballot_sync(0xffffffffu, pE);
        if (lane == 0) { sc[w] = __popc(balL); sc[8+w] = __popc(balE); }
        __syncthreads();
        if (t == 0) {
            unsigned a = 0, b = 0;
#pragma unroll
            for (int c = 0; c < 8; ++c) {
                unsigned x = sc[c];   sc[c]   = a; a += x;
                unsigned y = sc[8+c]; sc[8+c] = b; b += y;
            }
            sc[16] = a; sc[17] = b;
        }
        __syncthreads();
        int rL = (int)sc[w]   + __popc(balL & lm);
        int rE = (int)sc[8+w] + __popc(balE & lm);
        if (pL && runL + rL < cLess) sel[runL + rL] = j;
        if (pE && runE + rE < need)  sel[cLess + runE + rE] = j;
        runL += (int)sc[16]; runE += (int)sc[17];
        __syncthreads();
        if (runL >= cLess && runE >= need) break;
    }
}

// ---------------- kernel 2: distances + knn top20 + gumbel top40 ------------
__global__ __launch_bounds__(256) void row_kernel(
    const float* __restrict__ X, const int* __restrict__ batch,
    const int* __restrict__ xmask)
{
    __shared__ unsigned s_key[NN];          // 16 KB
    __shared__ unsigned s_hist[8][256];     // 8 KB (per-warp privatized)
    __shared__ unsigned sScan[10];
    __shared__ unsigned sColl[18];
    __shared__ int      sIdx[LRKK];
    const int i = blockIdx.x;
    const int t = threadIdx.x;
    const unsigned U_INV = __float_as_uint(1e30f);

    // Fully-masked row: all keys tie -> top_k returns lowest indices.
    if (xmask[i] != 0) {
        for (int e = t; e < EPN; e += 256)
            g_src[i*EPN + e] = (e < KNNK) ? e : (e - KNNK);
        return;
    }

    const float xi = X[3*i], yi = X[3*i+1], zi = X[3*i+2];
    const float x2i = __fadd_rn(__fadd_rn(__fmul_rn(xi,xi),__fmul_rn(yi,yi)),__fmul_rn(zi,zi));
    const int bi = batch[i];

    for (int j = t; j < NN; j += 256) {
        float xj = X[3*j], yj = X[3*j+1], zj = X[3*j+2];
        float x2j = __fadd_rn(__fadd_rn(__fmul_rn(xj,xj),__fmul_rn(yj,yj)),__fmul_rn(zj,zj));
        float dot = __fmul_rn(xi, xj);
        dot = __fmaf_rn(yi, yj, dot);
        dot = __fmaf_rn(zi, zj, dot);
        float d2  = fmaxf(__fsub_rn(__fadd_rn(x2i,x2j), __fmul_rn(2.0f,dot)), 0.0f);
        bool invalid = (batch[j] != bi) || (j == i) || (xmask[j] != 0);
        s_key[j] = invalid ? U_INV : __float_as_uint(d2);   // d2>=0 -> bits are order-preserving
    }
    __syncthreads();

    // ---- knn: 20 smallest d2 among valid
    uint2 rk = radix_select_k(s_key, s_hist, sScan, KNNK, U_INV, t);
    collect_k(s_key, rk.x, KNNK - (int)rk.y, (int)rk.y, sIdx, sColl, t);
    if (t < KNNK) g_src[i*EPN + t] = sIdx[t];
    if (t < KNNK) s_key[sIdx[t]] = U_INV;   // mark knn as invalid for lr stage
    __syncthreads();

    // ---- lr: transform to descending-order keys of (logit + gumbel)
    const unsigned INVK = __float_as_uint(-1e30f);  // key of sentinel lg=-1e30 (max valid-excluded)
    for (int j = t; j < NN; j += 256) {
        unsigned u = s_key[j];
        unsigned outk;
        if (u >= U_INV) outk = INVK;
        else {
            float d2 = __uint_as_float(u);
            float g = gumbel32((unsigned)(i*NN + j));
            float lg = __fadd_rn(__fmul_rn(-1.5f, logf(__fadd_rn(d2, 1e-6f))), g);
            unsigned m = __float_as_uint(lg);
            // descending-monotonic map: neg -> m ; pos -> ~m & 0x7FFFFFFF
            outk = (m & 0x80000000u) ? m : (~m & 0x7FFFFFFFu);
        }
        s_key[j] = outk;
    }
    __syncthreads();

    rk = radix_select_k(s_key, s_hist, sScan, LRKK, INVK, t);
    collect_k(s_key, rk.x, LRKK - (int)rk.y, (int)rk.y, sIdx, sColl, t);
    if (t < LRKK) g_src[i*EPN + KNNK + t] = sIdx[t];
}

// ---------------- kernel 3: edge MLP (2-edge ILP per warp) ------------------
__global__ __launch_bounds__(256) void edge_kernel(
    const float* __restrict__ X,
    const float* __restrict__ w1, const float* __restrict__ b1,
    const float* __restrict__ w2, const float* __restrict__ b2)
{
    __shared__ float sW1[AIN*HC];
    __shared__ float sW2[HC*HEADS];
    __shared__ float sB1[HC];
    __shared__ float sB2[HEADS];
    __shared__ float sA[8][2][AIN+2];
    const int t = threadIdx.x, lane = t & 31, warp = t >> 5;
    for (int idx = t; idx < AIN*HC; idx += 256) sW1[idx] = w1[idx];
    for (int idx = t; idx < HC*HEADS; idx += 256) sW2[idx] = w2[idx];
    if (t < HC)    sB1[t] = b1[t];
    if (t < HEADS) sB2[t] = b2[t];
    __syncthreads();

    const int e0 = blockIdx.x*EPB + warp*8;
    float* a0 = sA[warp][0];
    float* a1 = sA[warp][1];
    for (int r = 0; r < 8; r += 2) {
        const int eA = e0 + r, eB = eA + 1;
        const int iA = eA / EPN, iB = eB / EPN;
        const int sAi = g_src[eA], sBi = g_src[eB];
        for (int c = lane; c < SPH; c += 32) {
            a0[c]       = g_inv[sAi*SPH + c];
            a0[SPH + c] = g_inv[iA*SPH + c];
            a1[c]       = g_inv[sBi*SPH + c];
            a1[SPH + c] = g_inv[iB*SPH + c];
        }
        {
            const int half = lane >> 4;
            const int ll = lane & 15;
            const int ss = half ? sBi : sAi;
            const int ii = half ? iB : iA;
            float* aa = half ? a1 : a0;
            float dx = X[3*ss]-X[3*ii], dy = X[3*ss+1]-X[3*ii+1], dz = X[3*ss+2]-X[3*ii+2];
            float dist = sqrtf(__fadd_rn(__fadd_rn(__fmul_rn(dx,dx),__fmul_rn(dy,dy)),__fmul_rn(dz,dz)));
            float mu = (float)ll * (20.0f/15.0f);
            float zz = (dist - mu) / 1.25f;
            aa[2*SPH + ll] = expf(-zz*zz);
            if (ll < 8) {
                float fr = expf((float)(2*ll) * -0.5756462732485114f);
                float ang = (float)(ss - ii) * fr;
                aa[2*SPH + 16 + ll] = cosf(ang);
                aa[2*SPH + 24 + ll] = sinf(ang);
            }
        }
        __syncwarp();
        float h0 = sB1[lane], h1 = sB1[lane];
#pragma unroll 6
        for (int c = 0; c < AIN; ++c) {
            float wv = sW1[c*HC + lane];
            h0 = __fmaf_rn(a0[c], wv, h0);
            h1 = __fmaf_rn(a1[c], wv, h1);
        }
        h0 = h0 * (1.0f / (1.0f + expf(-h0)));
        h1 = h1 * (1.0f / (1.0f + expf(-h1)));
        float p0[HEADS], p1[HEADS];
#pragma unroll
        for (int hh = 0; hh < HEADS; ++hh) {
            p0[hh] = h0 * sW2[lane*HEADS + hh];
            p1[hh] = h1 * sW2[lane*HEADS + hh];
        }
#pragma unroll
        for (int off = 16; off; off >>= 1)
#pragma unroll
            for (int hh = 0; hh < HEADS; ++hh) {
                p0[hh] += __shfl_xor_sync(0xffffffffu, p0[hh], off);
                p1[hh] += __shfl_xor_sync(0xffffffffu, p1[hh], off);
            }
        if (lane == 0) {
#pragma unroll
            for (int hh = 0; hh < HEADS; ++hh) {
                g_logit[eA*HEADS + hh] = p0[hh] + sB2[hh];
                g_logit[eB*HEADS + hh] = p1[hh] + sB2[hh];
            }
        }
        __syncwarp();
    }
}

// ---------------- kernel 4: softmax + aggregate + epilogues -----------------
__global__ __launch_bounds__(256) void agg_kernel(
    const float* __restrict__ X, const float* __restrict__ bbr,
    const int* __restrict__ noise,
    const float* __restrict__ wo,   const float* __restrict__ bo,
    const float* __restrict__ wg,   const float* __restrict__ bg,
    const float* __restrict__ wf,   const float* __restrict__ bf,
    const float* __restrict__ wxca,
    const float* __restrict__ wgate, const float* __restrict__ bgate,
    const float* __restrict__ wbb,
    float* __restrict__ out)
{
    __shared__ float sal[EPN*HEADS];
    __shared__ int   ssrc[EPN];
    __shared__ float spart[4][LL*HV];   // 9.2 KB
    __shared__ float sagg[LL*HV];
    __shared__ float sout0[LL*BBC];
    __shared__ float soutf[LL*BBC];
    __shared__ float sgate[BBC];
    __shared__ float svec[3];
    __shared__ float sg2;
    __shared__ float subb[9];
    const int i = blockIdx.x;
    const int t = threadIdx.x;

    for (int idx = t; idx < EPN*HEADS; idx += 256) sal[idx] = g_logit[i*EPN*HEADS + idx];
    if (t < EPN) ssrc[t] = g_src[i*EPN + t];
    __syncthreads();

    if (t < HEADS) {
        float m = -3.4e38f;
        for (int e = 0; e < EPN; ++e) m = fmaxf(m, sal[e*HEADS + t]);
        float Z = 0.f;
        for (int e = 0; e < EPN; ++e) { float pp = expf(sal[e*HEADS+t] - m); sal[e*HEADS+t] = pp; Z += pp; }
        float inv = 1.0f / (Z + 1e-9f);
        for (int e = 0; e < EPN; ++e) sal[e*HEADS+t] *= inv;
    }
    __syncthreads();

    // gather-aggregate: 4 edge-groups x 15 edges for 4x MLP
    {
        const int d = t & 63, g = t >> 6;
        float acc[LL];
#pragma unroll
        for (int l = 0; l < LL; ++l) acc[l] = 0.f;
        const int h = d >> 3;
        for (int e = g; e < EPN; e += 4) {
            int s = ssrc[e];
            float al = sal[e*HEADS + h];
            const float* vp = g_v + (size_t)s*LL*HV + d;
#pragma unroll
            for (int l = 0; l < LL; ++l) acc[l] = __fmaf_rn(al, vp[l*HV], acc[l]);
        }
#pragma unroll
        for (int l = 0; l < LL; ++l) spart[g][l*HV + d] = acc[l];
    }
    __syncthreads();
    for (int idx = t; idx < LL*HV; idx += 256)
        sagg[idx] = ((spart[0][idx] + spart[1][idx]) + spart[2][idx]) + spart[3][idx];
    __syncthreads();

    // out0 = so3_linear(agg, wo, bo)
    for (int idx = t; idx < LL*BBC; idx += 256) {
        int l = idx >> 5, d = idx & 31;
        const float* w = wo + c_L3[l]*HV*BBC;
        float acc = 0.f;
#pragma unroll 8
        for (int c = 0; c < HV; ++c) acc = __fmaf_rn(sagg[l*HV + c], w[c*BBC + d], acc);
        if (l == 0) acc += bo[d];
        sout0[idx] = acc;
    }
    __syncthreads();

    if (t < BBC) {
        float g = 0.f;
        for (int c = 0; c < BBC; ++c) g = __fmaf_rn(sout0[c], wg[c*BBC + t], g);
        g += bg[t];
        sgate[t] = g * (1.0f / (1.0f + expf(-g)));
    }
    __syncthreads();

    for (int idx = t; idx < LL*BBC; idx += 256) {
        int l = idx >> 5, d = idx & 31;
        const float* w = wf + c_L3[l]*BBC*BBC;
        float acc = 0.f;
#pragma unroll 8
        for (int c = 0; c < BBC; ++c) acc = __fmaf_rn(sout0[l*BBC + c], w[c*BBC + d], acc);
        if (l == 0) acc += bf[d];
        float val = sout0[idx] + acc * sgate[d];
        soutf[idx] = val;
        out[OFF_OUT + (size_t)i*LL*BBC + idx] = val;
    }
    __syncthreads();

    if (t < 3) {
        float acc = 0.f;
        for (int c = 0; c < BBC; ++c) acc = __fmaf_rn(soutf[(1+t)*BBC + c], wxca[BBC + c], acc);
        svec[t] = acc;
    }
    if (t == 3) {
        float s = 0.f;
        for (int c = 0; c < BBC; ++c) s = __fmaf_rn(soutf[c], wgate[c], s);
        s += bgate[0];
        sg2 = fmaxf(s, 0.f) + log1pf(expf(-fabsf(s)));
    }
    if (t >= 8 && t < 17) {
        int idx = t - 8;
        int k = idx / 3, m = idx - 3*k;
        float acc = 0.f;
        for (int c = 0; c < BBC; ++c) acc = __fmaf_rn(soutf[(1+k)*BBC + c], wbb[(BBC + c)*NBB + m], acc);
        subb[idx] = acc;
    }
    __syncthreads();

    const int nz = noise[i];
    if (t < 3)
        out[(size_t)i*3 + t] = X[i*3+t] + (nz ? svec[t]*sg2 : 0.f);
    if (t >= 8 && t < 17) {
        int idx = t - 8;
        int m = idx / 3, k = idx - 3*m;
        out[OFF_BB + (size_t)i*9 + idx] = bbr[(size_t)i*9 + idx] + (nz ? subb[k*3 + m] : 0.f);
    }
}

// ---------------- launch ----------------------------------------------------
extern "C" void kernel_launch(void* const* d_in, const int* in_sizes, int n_in,
                              void* d_out, int out_size)
{
    const float* X      = (const float*)d_in[0];
    const float* bbr    = (const float*)d_in[1];
    const float* bbf    = (const float*)d_in[2];
    const int*   batch  = (const int*)d_in[3];
    const int*   xmask  = (const int*)d_in[4];
    const int*   noise  = (const int*)d_in[5];
    const float* w1     = (const float*)d_in[6];
    const float* b1     = (const float*)d_in[7];
    const float* w2     = (const float*)d_in[8];
    const float* b2     = (const float*)d_in[9];
    const float* wv     = (const float*)d_in[10];
    const float* bv     = (const float*)d_in[11];
    const float* wo     = (const float*)d_in[12];
    const float* bo     = (const float*)d_in[13];
    const float* wg     = (const float*)d_in[14];
    const float* bg     = (const float*)d_in[15];
    const float* wf     = (const float*)d_in[16];
    const float* bf     = (const float*)d_in[17];
    const float* wxca   = (const float*)d_in[18];
    const float* wgate  = (const float*)d_in[20];
    const float* bgate  = (const float*)d_in[21];
    const float* wbb    = (const float*)d_in[22];
    float* out = (float*)d_out;

    node_v_kernel<<<NN, 64>>>(bbf, bbr, noise, wv, bv);
    row_kernel<<<NN, 256>>>(X, batch, xmask);
    edge_kernel<<<NN*EPN/EPB, 256>>>(X, w1, b1, w2, b2);
    agg_kernel<<<NN, 256>>>(X, bbr, noise, wo, bo, wg, bg, wf, bf,
                            wxca, wgate, bgate, wbb, out);
}

// round 8
// speedup vs baseline: 2.1038x; 1.3510x over previous
#include <cuda_runtime.h>
#include <math.h>

// ---------------- problem constants ----------------
#define NN    4096
#define KNNK  20
#define LRKK  40
#define EPN   60
#define LL    9
#define SPH   35
#define BBC   32
#define NBB   3
#define HEADS 8
#define HV    64
#define HC    32
#define EPB   64

#define OFF_BB  (NN*3)
#define OFF_OUT (NN*3 + NN*9)

__device__ int   g_src[NN*EPN];
__device__ float g_logit[NN*EPN*HEADS];
__device__ float g_inv[NN*SPH];
__device__ float g_v[NN*LL*HV];
__device__ float g_hsrc[NN*HC];
__device__ float g_hdst[NN*HC];

__constant__ int c_L3[LL] = {0,1,1,1,2,2,2,2,2};

// ---------------- threefry2x32 gumbel (JAX partitionable path) --------------
__device__ __forceinline__ float gumbel32(unsigned int idx) {
    unsigned int x0 = 0u, x1 = idx;
    const unsigned int ks0 = 0u, ks1 = 1u, ks2 = 0x1BD11BDBu;
    x0 += ks0; x1 += ks1;
#define TFR(r) { x0 += x1; x1 = __funnelshift_l(x1, x1, (r)); x1 ^= x0; }
    TFR(13) TFR(15) TFR(26) TFR(6);  x0 += ks1; x1 += ks2 + 1u;
    TFR(17) TFR(29) TFR(16) TFR(24); x0 += ks2; x1 += ks0 + 2u;
    TFR(13) TFR(15) TFR(26) TFR(6);  x0 += ks0; x1 += ks1 + 3u;
    TFR(17) TFR(29) TFR(16) TFR(24); x0 += ks1; x1 += ks2 + 4u;
    TFR(13) TFR(15) TFR(26) TFR(6);  x0 += ks2; x1 += ks0 + 5u;
#undef TFR
    unsigned int bits = x0 ^ x1;
    float u = __uint_as_float((bits >> 9) | 0x3f800000u) - 1.0f;
    u = fmaxf(u, 1.17549435e-38f);
    return -logf(-logf(u));
}

// ---------------- kernel 1: node features + V + edge-MLP node partials ------
__global__ __launch_bounds__(64) void node_v_kernel(
    const float* __restrict__ bbf, const float* __restrict__ bbr,
    const int* __restrict__ noise,
    const float* __restrict__ wv, const float* __restrict__ bv,
    const float* __restrict__ w1, const float* __restrict__ b1)
{
    __shared__ float nf[LL*SPH];
    const int i = blockIdx.x;
    const int t = threadIdx.x;
    for (int idx = t; idx < LL*SPH; idx += 64) {
        int l = idx / SPH, c = idx - l*SPH;
        float v = 0.f;
        if (c < BBC)                    v = bbf[(i*LL + l)*BBC + c];
        else if (l >= 1 && l <= 3)      v = bbr[(i*NBB + (c-BBC))*3 + (l-1)];
        if (l == 0 && c == SPH-1)       v = noise[i] ? 1.0f : 0.0f;
        nf[idx] = v;
    }
    __syncthreads();
    if (t < SPH) g_inv[i*SPH + t] = nf[t];

    // edge-MLP node partials: h_src = inv@W1[0:35] + b1 ; h_dst = inv@W1[35:70]
    {
        if (t < HC) {
            float acc = b1[t];
#pragma unroll 7
            for (int c = 0; c < SPH; ++c) acc = __fmaf_rn(nf[c], w1[c*HC + t], acc);
            g_hsrc[i*HC + t] = acc;
        } else {
            int d = t - HC;
            float acc = 0.f;
#pragma unroll 7
            for (int c = 0; c < SPH; ++c) acc = __fmaf_rn(nf[c], w1[(SPH + c)*HC + d], acc);
            g_hdst[i*HC + d] = acc;
        }
    }

    const int d = t;
#pragma unroll
    for (int l = 0; l < LL; ++l) {
        const float* w = wv + c_L3[l]*SPH*HV;
        float acc = 0.f;
#pragma unroll 7
        for (int c = 0; c < SPH; ++c) acc = __fmaf_rn(nf[l*SPH + c], w[c*HV + d], acc);
        if (l == 0) acc += bv[d];
        g_v[(i*LL + l)*HV + d] = acc;
    }
}

// ---------------- radix-select helpers --------------------------------------
__device__ __forceinline__ uint2 radix_select_k(
    const unsigned* s_key, unsigned (*hist)[256], unsigned* sScan,
    unsigned k, unsigned validMax, int t)
{
    const int lane = t & 31, w = t >> 5;
    unsigned prefix = 0, kk = k;
#pragma unroll
    for (int byte = 3; byte >= 0; --byte) {
        const unsigned maskHi = (byte == 3) ? 0u : (0xFFFFFFFFu << (8*(byte+1)));
#pragma unroll
        for (int c = 0; c < 8; ++c) hist[c][t] = 0;
        __syncthreads();
        for (int j = t; j < NN; j += 256) {
            unsigned u = s_key[j];
            if (u < validMax && (u & maskHi) == prefix)
                atomicAdd(&hist[w][(u >> (8*byte)) & 255u], 1u);
        }
        __syncthreads();
        unsigned cnt = 0;
#pragma unroll
        for (int c = 0; c < 8; ++c) cnt += hist[c][t];
        unsigned v = cnt;
#pragma unroll
        for (int o = 1; o < 32; o <<= 1) {
            unsigned n = __shfl_up_sync(0xffffffffu, v, o);
            if (lane >= o) v += n;
        }
        if (lane == 31) sScan[w] = v;
        __syncthreads();
        if (t == 0) {
            unsigned a = 0;
#pragma unroll
            for (int c = 0; c < 8; ++c) { unsigned x = sScan[c]; sScan[c] = a; a += x; }
        }
        __syncthreads();
        unsigned incl = v + sScan[w];
        unsigned excl = incl - cnt;
        if (kk > excl && kk <= incl) { sScan[8] = (unsigned)t; sScan[9] = excl; }
        __syncthreads();
        prefix |= sScan[8] << (8*byte);
        kk -= sScan[9];
        __syncthreads();
    }
    return make_uint2(prefix, kk);
}

__device__ __forceinline__ void collect_k(
    const unsigned* s_key, unsigned T, int cLess, int need,
    int* sel, unsigned* sc, int t)
{
    const int lane = t & 31, w = t >> 5;
    const unsigned lm = (1u << lane) - 1u;
    int runL = 0, runE = 0;
    for (int base = 0; base < NN; base += 256) {
        const int j = base + t;
        const unsigned u = s_key[j];
        const bool pL = (u < T);
        const bool pE = (u == T);
        unsigned balL = __ballot_sync(0xffffffffu, pL);
        unsigned balE = __ballot_sync(0xffffffffu, pE);
        if (lane == 0) { sc[w] = __popc(balL); sc[8+w] = __popc(balE); }
        __syncthreads();
        if (t == 0) {
            unsigned a = 0, b = 0;
#pragma unroll
            for (int c = 0; c < 8; ++c) {
                unsigned x = sc[c];   sc[c]   = a; a += x;
                unsigned y = sc[8+c]; sc[8+c] = b; b += y;
            }
            sc[16] = a; sc[17] = b;
        }
        __syncthreads();
        int rL = (int)sc[w]   + __popc(balL & lm);
        int rE = (int)sc[8+w] + __popc(balE & lm);
        if (pL && runL + rL < cLess) sel[runL + rL] = j;
        if (pE && runE + rE < need)  sel[cLess + runE + rE] = j;
        runL += (int)sc[16]; runE += (int)sc[17];
        __syncthreads();
        if (runL >= cLess && runE >= need) break;
    }
}

// ---------------- kernel 2: distances + knn top20 + gumbel top40 ------------
__global__ __launch_bounds__(256) void row_kernel(
    const float* __restrict__ X, const int* __restrict__ batch,
    const int* __restrict__ xmask)
{
    __shared__ unsigned s_key[NN];
    __shared__ unsigned s_hist[8][256];
    __shared__ unsigned sScan[10];
    __shared__ unsigned sColl[18];
    __shared__ int      sIdx[LRKK];
    const int i = blockIdx.x;
    const int t = threadIdx.x;
    const unsigned U_INV = __float_as_uint(1e30f);

    if (xmask[i] != 0) {
        for (int e = t; e < EPN; e += 256)
            g_src[i*EPN + e] = (e < KNNK) ? e : (e - KNNK);
        return;
    }

    const float xi = X[3*i], yi = X[3*i+1], zi = X[3*i+2];
    const float x2i = __fadd_rn(__fadd_rn(__fmul_rn(xi,xi),__fmul_rn(yi,yi)),__fmul_rn(zi,zi));
    const int bi = batch[i];

    for (int j = t; j < NN; j += 256) {
        float xj = X[3*j], yj = X[3*j+1], zj = X[3*j+2];
        float x2j = __fadd_rn(__fadd_rn(__fmul_rn(xj,xj),__fmul_rn(yj,yj)),__fmul_rn(zj,zj));
        float dot = __fmul_rn(xi, xj);
        dot = __fmaf_rn(yi, yj, dot);
        dot = __fmaf_rn(zi, zj, dot);
        float d2  = fmaxf(__fsub_rn(__fadd_rn(x2i,x2j), __fmul_rn(2.0f,dot)), 0.0f);
        bool invalid = (batch[j] != bi) || (j == i) || (xmask[j] != 0);
        s_key[j] = invalid ? U_INV : __float_as_uint(d2);
    }
    __syncthreads();

    uint2 rk = radix_select_k(s_key, s_hist, sScan, KNNK, U_INV, t);
    collect_k(s_key, rk.x, KNNK - (int)rk.y, (int)rk.y, sIdx, sColl, t);
    if (t < KNNK) g_src[i*EPN + t] = sIdx[t];
    if (t < KNNK) s_key[sIdx[t]] = U_INV;
    __syncthreads();

    const unsigned INVK = __float_as_uint(-1e30f);
    for (int j = t; j < NN; j += 256) {
        unsigned u = s_key[j];
        unsigned outk;
        if (u >= U_INV) outk = INVK;
        else {
            float d2 = __uint_as_float(u);
            float g = gumbel32((unsigned)(i*NN + j));
            float lg = __fadd_rn(__fmul_rn(-1.5f, logf(__fadd_rn(d2, 1e-6f))), g);
            unsigned m = __float_as_uint(lg);
            outk = (m & 0x80000000u) ? m : (~m & 0x7FFFFFFFu);
        }
        s_key[j] = outk;
    }
    __syncthreads();

    rk = radix_select_k(s_key, s_hist, sScan, LRKK, INVK, t);
    collect_k(s_key, rk.x, LRKK - (int)rk.y, (int)rk.y, sIdx, sColl, t);
    if (t < LRKK) g_src[i*EPN + KNNK + t] = sIdx[t];
}

// ---------------- kernel 3: edge MLP (factorized; 8 edges per warp) ---------
__global__ __launch_bounds__(256) void edge_kernel(
    const float* __restrict__ X,
    const float* __restrict__ w1,
    const float* __restrict__ w2, const float* __restrict__ b2)
{
    __shared__ float sW1e[32*HC];      // W1 rows 70..101 (edge-feat part)
    __shared__ float sW2[HC*HEADS];
    __shared__ float sB2[HEADS];
    __shared__ float sEF[8][8][36];    // [warp][edge][feat]
    __shared__ float sH[8][8][36];     // [warp][edge][hidden]
    const int t = threadIdx.x, lane = t & 31, warp = t >> 5;
    for (int idx = t; idx < 32*HC; idx += 256) sW1e[idx] = w1[(2*SPH)*HC + idx];
    for (int idx = t; idx < HC*HEADS; idx += 256) sW2[idx] = w2[idx];
    if (t < HEADS) sB2[t] = b2[t];
    __syncthreads();

    const int e0 = blockIdx.x*EPB + warp*8;

    // ---- stage A: edge features (4 lanes per edge, 8 feats each)
    {
        const int e = lane >> 2, q = lane & 3;
        const int edge = e0 + e;
        const int ii = edge / EPN;
        const int ss = g_src[edge];
        float dx = X[3*ss]-X[3*ii], dy = X[3*ss+1]-X[3*ii+1], dz = X[3*ss+2]-X[3*ii+2];
        float dist = sqrtf(__fadd_rn(__fadd_rn(__fmul_rn(dx,dx),__fmul_rn(dy,dy)),__fmul_rn(dz,dz)));
        if (q < 2) {
#pragma unroll
            for (int r = 0; r < 8; ++r) {
                int f = q*8 + r;
                float mu = (float)f * (20.0f/15.0f);
                float zz = (dist - mu) * 0.8f;   // /1.25
                sEF[warp][e][f] = expf(-zz*zz);
            }
        } else {
            float dfl = (float)(ss - ii);
#pragma unroll
            for (int r = 0; r < 4; ++r) {
                int k = (q-2)*4 + r;
                float fr = expf((float)(2*k) * -0.5756462732485114f);
                float sv, cv;
                sincosf(dfl * fr, &sv, &cv);
                sEF[warp][e][16 + k] = cv;
                sEF[warp][e][24 + k] = sv;
            }
        }
    }
    __syncwarp();

    // ---- stage B: hidden units (lane = hidden unit, 8 edges in regs)
    {
        float h[8];
#pragma unroll
        for (int e = 0; e < 8; ++e) {
            const int edge = e0 + e;
            const int ii = edge / EPN;
            const int ss = g_src[edge];
            h[e] = g_hsrc[ss*HC + lane] + g_hdst[ii*HC + lane];
        }
#pragma unroll 4
        for (int c = 0; c < 32; ++c) {
            float wv = sW1e[c*HC + lane];
#pragma unroll
            for (int e = 0; e < 8; ++e)
                h[e] = __fmaf_rn(sEF[warp][e][c], wv, h[e]);
        }
#pragma unroll
        for (int e = 0; e < 8; ++e) {
            float hv = h[e];
            sH[warp][e][lane] = hv * (1.0f / (1.0f + expf(-hv)));
        }
    }
    __syncwarp();

    // ---- stage C: logits (lane -> edge = lane>>2, heads lane&3 and +4)
    {
        const int e = lane >> 2;
        const int h0 = lane & 3, h1 = h0 + 4;
        float a0 = sB2[h0], a1 = sB2[h1];
#pragma unroll 8
        for (int c = 0; c < 32; ++c) {
            float hv = sH[warp][e][c];
            a0 = __fmaf_rn(hv, sW2[c*HEADS + h0], a0);
            a1 = __fmaf_rn(hv, sW2[c*HEADS + h1], a1);
        }
        g_logit[(e0+e)*HEADS + h0] = a0;
        g_logit[(e0+e)*HEADS + h1] = a1;
    }
}

// ---------------- kernel 4: softmax + aggregate + epilogues -----------------
__global__ __launch_bounds__(256) void agg_kernel(
    const float* __restrict__ X, const float* __restrict__ bbr,
    const int* __restrict__ noise,
    const float* __restrict__ wo,   const float* __restrict__ bo,
    const float* __restrict__ wg,   const float* __restrict__ bg,
    const float* __restrict__ wf,   const float* __restrict__ bf,
    const float* __restrict__ wxca,
    const float* __restrict__ wgate, const float* __restrict__ bgate,
    const float* __restrict__ wbb,
    float* __restrict__ out)
{
    __shared__ float sal[EPN*HEADS];
    __shared__ int   ssrc[EPN];
    __shared__ float spart[4][LL*HV];
    __shared__ float sagg[LL*HV];
    __shared__ float sout0[LL*BBC];
    __shared__ float soutf[LL*BBC];
    __shared__ float sgate[BBC];
    __shared__ float svec[3];
    __shared__ float sg2;
    __shared__ float subb[9];
    const int i = blockIdx.x;
    const int t = threadIdx.x;

    for (int idx = t; idx < EPN*HEADS; idx += 256) sal[idx] = g_logit[i*EPN*HEADS + idx];
    if (t < EPN) ssrc[t] = g_src[i*EPN + t];
    __syncthreads();

    if (t < HEADS) {
        float m = -3.4e38f;
        for (int e = 0; e < EPN; ++e) m = fmaxf(m, sal[e*HEADS + t]);
        float Z = 0.f;
        for (int e = 0; e < EPN; ++e) { float pp = expf(sal[e*HEADS+t] - m); sal[e*HEADS+t] = pp; Z += pp; }
        float inv = 1.0f / (Z + 1e-9f);
        for (int e = 0; e < EPN; ++e) sal[e*HEADS+t] *= inv;
    }
    __syncthreads();

    // gather-aggregate: 4 edge-groups, 2-edge unroll for doubled MLP
    {
        const int d = t & 63, g = t >> 6;
        float acc[LL];
#pragma unroll
        for (int l = 0; l < LL; ++l) acc[l] = 0.f;
        const int h = d >> 3;
        for (int e = g; e < EPN; e += 8) {
            const int e2 = e + 4;
            const bool has2 = (e2 < EPN);
            int s0 = ssrc[e];
            int s1 = has2 ? ssrc[e2] : s0;
            float al0 = sal[e*HEADS + h];
            float al1 = has2 ? sal[e2*HEADS + h] : 0.f;
            const float* p0 = g_v + (size_t)s0*LL*HV + d;
            const float* p1 = g_v + (size_t)s1*LL*HV + d;
#pragma unroll
            for (int l = 0; l < LL; ++l) {
                float a = p0[l*HV];
                float b = p1[l*HV];
                acc[l] = __fmaf_rn(al0, a, __fmaf_rn(al1, b, acc[l]));
            }
        }
#pragma unroll
        for (int l = 0; l < LL; ++l) spart[g][l*HV + d] = acc[l];
    }
    __syncthreads();
    for (int idx = t; idx < LL*HV; idx += 256)
        sagg[idx] = ((spart[0][idx] + spart[1][idx]) + spart[2][idx]) + spart[3][idx];
    __syncthreads();

    for (int idx = t; idx < LL*BBC; idx += 256) {
        int l = idx >> 5, d = idx & 31;
        const float* w = wo + c_L3[l]*HV*BBC;
        float acc = 0.f;
#pragma unroll 8
        for (int c = 0; c < HV; ++c) acc = __fmaf_rn(sagg[l*HV + c], w[c*BBC + d], acc);
        if (l == 0) acc += bo[d];
        sout0[idx] = acc;
    }
    __syncthreads();

    if (t < BBC) {
        float g = 0.f;
        for (int c = 0; c < BBC; ++c) g = __fmaf_rn(sout0[c], wg[c*BBC + t], g);
        g += bg[t];
        sgate[t] = g * (1.0f / (1.0f + expf(-g)));
    }
    __syncthreads();

    for (int idx = t; idx < LL*BBC; idx += 256) {
        int l = idx >> 5, d = idx & 31;
        const float* w = wf + c_L3[l]*BBC*BBC;
        float acc = 0.f;
#pragma unroll 8
        for (int c = 0; c < BBC; ++c) acc = __fmaf_rn(sout0[l*BBC + c], w[c*BBC + d], acc);
        if (l == 0) acc += bf[d];
        float val = sout0[idx] + acc * sgate[d];
        soutf[idx] = val;
        out[OFF_OUT + (size_t)i*LL*BBC + idx] = val;
    }
    __syncthreads();

    if (t < 3) {
        float acc = 0.f;
        for (int c = 0; c < BBC; ++c) acc = __fmaf_rn(soutf[(1+t)*BBC + c], wxca[BBC + c], acc);
        svec[t] = acc;
    }
    if (t == 3) {
        float s = 0.f;
        for (int c = 0; c < BBC; ++c) s = __fmaf_rn(soutf[c], wgate[c], s);
        s += bgate[0];
        sg2 = fmaxf(s, 0.f) + log1pf(expf(-fabsf(s)));
    }
    if (t >= 8 && t < 17) {
        int idx = t - 8;
        int k = idx / 3, m = idx - 3*k;
        float acc = 0.f;
        for (int c = 0; c < BBC; ++c) acc = __fmaf_rn(soutf[(1+k)*BBC + c], wbb[(BBC + c)*NBB + m], acc);
        subb[idx] = acc;
    }
    __syncthreads();

    const int nz = noise[i];
    if (t < 3)
        out[(size_t)i*3 + t] = X[i*3+t] + (nz ? svec[t]*sg2 : 0.f);
    if (t >= 8 && t < 17) {
        int idx = t - 8;
        int m = idx / 3, k = idx - 3*m;
        out[OFF_BB + (size_t)i*9 + idx] = bbr[(size_t)i*9 + idx] + (nz ? subb[k*3 + m] : 0.f);
    }
}

// ---------------- launch ----------------------------------------------------
extern "C" void kernel_launch(void* const* d_in, const int* in_sizes, int n_in,
                              void* d_out, int out_size)
{
    const float* X      = (const float*)d_in[0];
    const float* bbr    = (const float*)d_in[1];
    const float* bbf    = (const float*)d_in[2];
    const int*   batch  = (const int*)d_in[3];
    const int*   xmask  = (const int*)d_in[4];
    const int*   noise  = (const int*)d_in[5];
    const float* w1     = (const float*)d_in[6];
    const float* b1     = (const float*)d_in[7];
    const float* w2     = (const float*)d_in[8];
    const float* b2     = (const float*)d_in[9];
    const float* wv     = (const float*)d_in[10];
    const float* bv     = (const float*)d_in[11];
    const float* wo     = (const float*)d_in[12];
    const float* bo     = (const float*)d_in[13];
    const float* wg     = (const float*)d_in[14];
    const float* bg     = (const float*)d_in[15];
    const float* wf     = (const float*)d_in[16];
    const float* bf     = (const float*)d_in[17];
    const float* wxca   = (const float*)d_in[18];
    const float* wgate  = (const float*)d_in[20];
    const float* bgate  = (const float*)d_in[21];
    const float* wbb    = (const float*)d_in[22];
    float* out = (float*)d_out;

    node_v_kernel<<<NN, 64>>>(bbf, bbr, noise, wv, bv, w1, b1);
    row_kernel<<<NN, 256>>>(X, batch, xmask);
    edge_kernel<<<NN*EPN/EPB, 256>>>(X, w1, w2, b2);
    agg_kernel<<<NN, 256>>>(X, bbr, noise, wo, bo, wg, bg, wf, bf,
                            wxca, wgate, bgate, wbb, out);
}

// round 9
// speedup vs baseline: 2.2149x; 1.0528x over previous
#include <cuda_runtime.h>
#include <cuda_fp16.h>
#include <math.h>

// ---------------- problem constants ----------------
#define NN    4096
#define KNNK  20
#define LRKK  40
#define EPN   60
#define LL    9
#define SPH   35
#define BBC   32
#define NBB   3
#define HEADS 8
#define HV    64
#define HC    32
#define EPB   64
#define NVB   8      // nodes per node_v block

#define OFF_BB  (NN*3)
#define OFF_OUT (NN*3 + NN*9)

__device__ int     g_src[NN*EPN];
__device__ float   g_logit[NN*EPN*HEADS];
__device__ float   g_inv[NN*SPH];
__device__ __half2 g_vh[NN*HV*5];          // [node][d][5 half2] = 9 v-values + pad
__device__ float   g_hsrc[NN*HC];
__device__ float   g_hdst[NN*HC];

__constant__ int c_L3[LL] = {0,1,1,1,2,2,2,2,2};

// ---------------- threefry2x32 gumbel (JAX partitionable path) --------------
__device__ __forceinline__ float gumbel32(unsigned int idx) {
    unsigned int x0 = 0u, x1 = idx;
    const unsigned int ks0 = 0u, ks1 = 1u, ks2 = 0x1BD11BDBu;
    x0 += ks0; x1 += ks1;
#define TFR(r) { x0 += x1; x1 = __funnelshift_l(x1, x1, (r)); x1 ^= x0; }
    TFR(13) TFR(15) TFR(26) TFR(6);  x0 += ks1; x1 += ks2 + 1u;
    TFR(17) TFR(29) TFR(16) TFR(24); x0 += ks2; x1 += ks0 + 2u;
    TFR(13) TFR(15) TFR(26) TFR(6);  x0 += ks0; x1 += ks1 + 3u;
    TFR(17) TFR(29) TFR(16) TFR(24); x0 += ks1; x1 += ks2 + 4u;
    TFR(13) TFR(15) TFR(26) TFR(6);  x0 += ks2; x1 += ks0 + 5u;
#undef TFR
    unsigned int bits = x0 ^ x1;
    float u = __uint_as_float((bits >> 9) | 0x3f800000u) - 1.0f;
    u = fmaxf(u, 1.17549435e-38f);
    return -logf(-logf(u));
}

// ---------------- kernel 1: node features + V(fp16) + edge-MLP partials -----
__global__ __launch_bounds__(512) void node_v_kernel(
    const float* __restrict__ bbf, const float* __restrict__ bbr,
    const int* __restrict__ noise,
    const float* __restrict__ wv, const float* __restrict__ bv,
    const float* __restrict__ w1, const float* __restrict__ b1)
{
    __shared__ float sWV[3*SPH*HV];     // 26880 B
    __shared__ float sW1[2*SPH*HC];     // 8960 B
    __shared__ float nf[NVB][LL*SPH];   // 10080 B
    const int t = threadIdx.x;
    for (int idx = t; idx < 3*SPH*HV; idx += 512) sWV[idx] = wv[idx];
    for (int idx = t; idx < 2*SPH*HC; idx += 512) sW1[idx] = w1[idx];

    const int g = t >> 6;        // node sub-group 0..7
    const int tt = t & 63;
    const int i = blockIdx.x*NVB + g;

    for (int idx = tt; idx < LL*SPH; idx += 64) {
        int l = idx / SPH, c = idx - l*SPH;
        float v = 0.f;
        if (c < BBC)                    v = bbf[(i*LL + l)*BBC + c];
        else if (l >= 1 && l <= 3)      v = bbr[(i*NBB + (c-BBC))*3 + (l-1)];
        if (l == 0 && c == SPH-1)       v = noise[i] ? 1.0f : 0.0f;
        nf[g][idx] = v;
    }
    __syncthreads();
    if (tt < SPH) g_inv[i*SPH + tt] = nf[g][tt];

    // edge-MLP node partials
    if (tt < HC) {
        float acc = b1[tt];
#pragma unroll 7
        for (int c = 0; c < SPH; ++c) acc = __fmaf_rn(nf[g][c], sW1[c*HC + tt], acc);
        g_hsrc[i*HC + tt] = acc;
    } else {
        int d = tt - HC;
        float acc = 0.f;
#pragma unroll 7
        for (int c = 0; c < SPH; ++c) acc = __fmaf_rn(nf[g][c], sW1[(SPH + c)*HC + d], acc);
        g_hdst[i*HC + d] = acc;
    }

    // V = so3_linear(node, wv, bv) -> fp16 packed [d][5 half2]
    {
        const int d = tt;
        float va[LL];
#pragma unroll
        for (int l = 0; l < LL; ++l) {
            const float* w = sWV + c_L3[l]*SPH*HV;
            float acc = 0.f;
#pragma unroll 7
            for (int c = 0; c < SPH; ++c) acc = __fmaf_rn(nf[g][l*SPH + c], w[c*HV + d], acc);
            if (l == 0) acc += bv[d];
            va[l] = acc;
        }
        __half2* dst = g_vh + ((size_t)i*HV + d)*5;
        dst[0] = __floats2half2_rn(va[0], va[1]);
        dst[1] = __floats2half2_rn(va[2], va[3]);
        dst[2] = __floats2half2_rn(va[4], va[5]);
        dst[3] = __floats2half2_rn(va[6], va[7]);
        dst[4] = __floats2half2_rn(va[8], 0.f);
    }
}

// ---------------- radix-select helpers --------------------------------------
// PRE=true: caller already built the byte-3 histogram (fused with key fill).
template<bool PRE>
__device__ __forceinline__ uint2 radix_select_k(
    const unsigned* s_key, unsigned (*hist)[256], unsigned* sScan,
    unsigned k, unsigned validMax, int t)
{
    const int lane = t & 31, w = t >> 5;
    unsigned prefix = 0, kk = k;
#pragma unroll
    for (int byte = 3; byte >= 0; --byte) {
        const unsigned maskHi = (byte == 3) ? 0u : (0xFFFFFFFFu << (8*(byte+1)));
        if (!(PRE && byte == 3)) {
#pragma unroll
            for (int c = 0; c < 8; ++c) hist[c][t] = 0;
            __syncthreads();
            for (int j = t; j < NN; j += 256) {
                unsigned u = s_key[j];
                if (u < validMax && (u & maskHi) == prefix)
                    atomicAdd(&hist[w][(u >> (8*byte)) & 255u], 1u);
            }
            __syncthreads();
        }
        unsigned cnt = 0;
#pragma unroll
        for (int c = 0; c < 8; ++c) cnt += hist[c][t];
        unsigned v = cnt;
#pragma unroll
        for (int o = 1; o < 32; o <<= 1) {
            unsigned n = __shfl_up_sync(0xffffffffu, v, o);
            if (lane >= o) v += n;
        }
        if (lane == 31) sScan[w] = v;
        __syncthreads();
        if (t == 0) {
            unsigned a = 0;
#pragma unroll
            for (int c = 0; c < 8; ++c) { unsigned x = sScan[c]; sScan[c] = a; a += x; }
        }
        __syncthreads();
        unsigned incl = v + sScan[w];
        unsigned excl = incl - cnt;
        if (kk > excl && kk <= incl) { sScan[8] = (unsigned)t; sScan[9] = excl; }
        __syncthreads();
        prefix |= sScan[8] << (8*byte);
        kk -= sScan[9];
        __syncthreads();
    }
    return make_uint2(prefix, kk);
}

__device__ __forceinline__ void collect_k(
    const unsigned* s_key, unsigned T, int cLess, int need,
    int* sel, unsigned* sc, int t)
{
    const int lane = t & 31, w = t >> 5;
    const unsigned lm = (1u << lane) - 1u;
    int runL = 0, runE = 0;
    for (int base = 0; base < NN; base += 256) {
        const int j = base + t;
        const unsigned u = s_key[j];
        const bool pL = (u < T);
        const bool pE = (u == T);
        unsigned balL = __ballot_sync(0xffffffffu, pL);
        unsigned balE = __ballot_sync(0xffffffffu, pE);
        if (lane == 0) { sc[w] = __popc(balL); sc[8+w] = __popc(balE); }
        __syncthreads();
        if (t == 0) {
            unsigned a = 0, b = 0;
#pragma unroll
            for (int c = 0; c < 8; ++c) {
                unsigned x = sc[c];   sc[c]   = a; a += x;
                unsigned y = sc[8+c]; sc[8+c] = b; b += y;
            }
            sc[16] = a; sc[17] = b;
        }
        __syncthreads();
        int rL = (int)sc[w]   + __popc(balL & lm);
        int rE = (int)sc[8+w] + __popc(balE & lm);
        if (pL && runL + rL < cLess) sel[runL + rL] = j;
        if (pE && runE + rE < need)  sel[cLess + runE + rE] = j;
        runL += (int)sc[16]; runE += (int)sc[17];
        __syncthreads();
        if (runL >= cLess && runE >= need) break;
    }
}

// ---------------- kernel 2: distances + knn top20 + gumbel top40 ------------
__global__ __launch_bounds__(256) void row_kernel(
    const float* __restrict__ X, const int* __restrict__ batch,
    const int* __restrict__ xmask)
{
    __shared__ unsigned s_key[NN];
    __shared__ unsigned s_hist[8][256];
    __shared__ unsigned sScan[10];
    __shared__ unsigned sColl[18];
    __shared__ int      sIdx[LRKK];
    const int i = blockIdx.x;
    const int t = threadIdx.x;
    const int w = t >> 5;
    const unsigned U_INV = __float_as_uint(1e30f);

    if (xmask[i] != 0) {
        for (int e = t; e < EPN; e += 256)
            g_src[i*EPN + e] = (e < KNNK) ? e : (e - KNNK);
        return;
    }

    const float xi = X[3*i], yi = X[3*i+1], zi = X[3*i+2];
    const float x2i = __fadd_rn(__fadd_rn(__fmul_rn(xi,xi),__fmul_rn(yi,yi)),__fmul_rn(zi,zi));
    const int bi = batch[i];

    // fill keys + fused byte-3 histogram
#pragma unroll
    for (int c = 0; c < 8; ++c) s_hist[c][t] = 0;
    __syncthreads();
    for (int j = t; j < NN; j += 256) {
        float xj = X[3*j], yj = X[3*j+1], zj = X[3*j+2];
        float x2j = __fadd_rn(__fadd_rn(__fmul_rn(xj,xj),__fmul_rn(yj,yj)),__fmul_rn(zj,zj));
        float dot = __fmul_rn(xi, xj);
        dot = __fmaf_rn(yi, yj, dot);
        dot = __fmaf_rn(zi, zj, dot);
        float d2  = fmaxf(__fsub_rn(__fadd_rn(x2i,x2j), __fmul_rn(2.0f,dot)), 0.0f);
        bool invalid = (batch[j] != bi) || (j == i) || (xmask[j] != 0);
        unsigned u = invalid ? U_INV : __float_as_uint(d2);
        s_key[j] = u;
        if (!invalid) atomicAdd(&s_hist[w][u >> 24], 1u);
    }
    __syncthreads();

    uint2 rk = radix_select_k<true>(s_key, s_hist, sScan, KNNK, U_INV, t);
    collect_k(s_key, rk.x, KNNK - (int)rk.y, (int)rk.y, sIdx, sColl, t);
    if (t < KNNK) g_src[i*EPN + t] = sIdx[t];
    if (t < KNNK) s_key[sIdx[t]] = U_INV;
    __syncthreads();

    // lr transform + fused byte-3 histogram
    const unsigned INVK = __float_as_uint(-1e30f);
#pragma unroll
    for (int c = 0; c < 8; ++c) s_hist[c][t] = 0;
    __syncthreads();
    for (int j = t; j < NN; j += 256) {
        unsigned u = s_key[j];
        unsigned outk;
        if (u >= U_INV) outk = INVK;
        else {
            float d2 = __uint_as_float(u);
            float g = gumbel32((unsigned)(i*NN + j));
            float lg = __fadd_rn(__fmul_rn(-1.5f, logf(__fadd_rn(d2, 1e-6f))), g);
            unsigned m = __float_as_uint(lg);
            outk = (m & 0x80000000u) ? m : (~m & 0x7FFFFFFFu);
            atomicAdd(&s_hist[w][outk >> 24], 1u);
        }
        s_key[j] = outk;
    }
    __syncthreads();

    rk = radix_select_k<true>(s_key, s_hist, sScan, LRKK, INVK, t);
    collect_k(s_key, rk.x, LRKK - (int)rk.y, (int)rk.y, sIdx, sColl, t);
    if (t < LRKK) g_src[i*EPN + KNNK + t] = sIdx[t];
}

// ---------------- kernel 3: edge MLP (factorized; 8 edges per warp) ---------
__global__ __launch_bounds__(256) void edge_kernel(
    const float* __restrict__ X,
    const float* __restrict__ w1,
    const float* __restrict__ w2, const float* __restrict__ b2)
{
    __shared__ float sW1e[32*HC];
    __shared__ float sW2[HC*HEADS];
    __shared__ float sB2[HEADS];
    __shared__ float sEF[8][8][36];
    __shared__ float sH[8][8][36];
    const int t = threadIdx.x, lane = t & 31, warp = t >> 5;
    for (int idx = t; idx < 32*HC; idx += 256) sW1e[idx] = w1[(2*SPH)*HC + idx];
    for (int idx = t; idx < HC*HEADS; idx += 256) sW2[idx] = w2[idx];
    if (t < HEADS) sB2[t] = b2[t];
    __syncthreads();

    const int e0 = blockIdx.x*EPB + warp*8;

    {
        const int e = lane >> 2, q = lane & 3;
        const int edge = e0 + e;
        const int ii = edge / EPN;
        const int ss = g_src[edge];
        float dx = X[3*ss]-X[3*ii], dy = X[3*ss+1]-X[3*ii+1], dz = X[3*ss+2]-X[3*ii+2];
        float dist = sqrtf(__fadd_rn(__fadd_rn(__fmul_rn(dx,dx),__fmul_rn(dy,dy)),__fmul_rn(dz,dz)));
        if (q < 2) {
#pragma unroll
            for (int r = 0; r < 8; ++r) {
                int f = q*8 + r;
                float mu = (float)f * (20.0f/15.0f);
                float zz = (dist - mu) * 0.8f;
                sEF[warp][e][f] = expf(-zz*zz);
            }
        } else {
            float dfl = (float)(ss - ii);
#pragma unroll
            for (int r = 0; r < 4; ++r) {
                int k = (q-2)*4 + r;
                float fr = expf((float)(2*k) * -0.5756462732485114f);
                float sv, cv;
                sincosf(dfl * fr, &sv, &cv);
                sEF[warp][e][16 + k] = cv;
                sEF[warp][e][24 + k] = sv;
            }
        }
    }
    __syncwarp();

    {
        float h[8];
#pragma unroll
        for (int e = 0; e < 8; ++e) {
            const int edge = e0 + e;
            const int ii = edge / EPN;
            const int ss = g_src[edge];
            h[e] = g_hsrc[ss*HC + lane] + g_hdst[ii*HC + lane];
        }
#pragma unroll 4
        for (int c = 0; c < 32; ++c) {
            float wv = sW1e[c*HC + lane];
#pragma unroll
            for (int e = 0; e < 8; ++e)
                h[e] = __fmaf_rn(sEF[warp][e][c], wv, h[e]);
        }
#pragma unroll
        for (int e = 0; e < 8; ++e) {
            float hv = h[e];
            sH[warp][e][lane] = hv * (1.0f / (1.0f + expf(-hv)));
        }
    }
    __syncwarp();

    {
        const int e = lane >> 2;
        const int h0 = lane & 3, h1 = h0 + 4;
        float a0 = sB2[h0], a1 = sB2[h1];
#pragma unroll 8
        for (int c = 0; c < 32; ++c) {
            float hv = sH[warp][e][c];
            a0 = __fmaf_rn(hv, sW2[c*HEADS + h0], a0);
            a1 = __fmaf_rn(hv, sW2[c*HEADS + h1], a1);
        }
        g_logit[(e0+e)*HEADS + h0] = a0;
        g_logit[(e0+e)*HEADS + h1] = a1;
    }
}

// ---------------- kernel 4: softmax + aggregate + epilogues -----------------
__global__ __launch_bounds__(256) void agg_kernel(
    const float* __restrict__ X, const float* __restrict__ bbr,
    const int* __restrict__ noise,
    const float* __restrict__ wo,   const float* __restrict__ bo,
    const float* __restrict__ wg,   const float* __restrict__ bg,
    const float* __restrict__ wf,   const float* __restrict__ bf,
    const float* __restrict__ wxca,
    const float* __restrict__ wgate, const float* __restrict__ bgate,
    const float* __restrict__ wbb,
    float* __restrict__ out)
{
    __shared__ float sal[EPN*HEADS];
    __shared__ int   ssrc[EPN];
    __shared__ float spart[4][LL*HV];
    __shared__ float sagg[LL*HV];
    __shared__ float sout0[LL*BBC];
    __shared__ float soutf[LL*BBC];
    __shared__ float sgate[BBC];
    __shared__ float svec[3];
    __shared__ float sg2;
    __shared__ float subb[9];
    const int i = blockIdx.x;
    const int t = threadIdx.x;

    for (int idx = t; idx < EPN*HEADS; idx += 256) sal[idx] = g_logit[i*EPN*HEADS + idx];
    if (t < EPN) ssrc[t] = g_src[i*EPN + t];
    __syncthreads();

    // softmax per head: 8 threads per head
    if (t < 64) {
        const int h = t >> 3, sub = t & 7;
        float m = -3.4e38f;
        for (int e = sub; e < EPN; e += 8) m = fmaxf(m, sal[e*HEADS + h]);
#pragma unroll
        for (int o = 1; o < 8; o <<= 1) m = fmaxf(m, __shfl_xor_sync(0xffffffffu, m, o, 8));
        float Z = 0.f;
        for (int e = sub; e < EPN; e += 8) {
            float pp = expf(sal[e*HEADS + h] - m);
            sal[e*HEADS + h] = pp;
            Z += pp;
        }
#pragma unroll
        for (int o = 1; o < 8; o <<= 1) Z += __shfl_xor_sync(0xffffffffu, Z, o, 8);
        float inv = 1.0f / (Z + 1e-9f);
        for (int e = sub; e < EPN; e += 8) sal[e*HEADS + h] *= inv;
    }
    __syncthreads();

    // gather-aggregate from fp16 v (2-edge unroll, 10 half2 loads in flight)
    {
        const int d = t & 63, g = t >> 6;
        float acc[LL];
#pragma unroll
        for (int l = 0; l < LL; ++l) acc[l] = 0.f;
        const int h = d >> 3;
        for (int e = g; e < EPN; e += 8) {
            const int e2 = e + 4;
            const bool has2 = (e2 < EPN);
            int s0 = ssrc[e];
            int s1 = has2 ? ssrc[e2] : s0;
            float al0 = sal[e*HEADS + h];
            float al1 = has2 ? sal[e2*HEADS + h] : 0.f;
            const __half2* p0 = g_vh + ((size_t)s0*HV + d)*5;
            const __half2* p1 = g_vh + ((size_t)s1*HV + d)*5;
#pragma unroll
            for (int k = 0; k < 4; ++k) {
                float2 f0 = __half22float2(p0[k]);
                float2 f1 = __half22float2(p1[k]);
                acc[2*k]   = __fmaf_rn(al0, f0.x, __fmaf_rn(al1, f1.x, acc[2*k]));
                acc[2*k+1] = __fmaf_rn(al0, f0.y, __fmaf_rn(al1, f1.y, acc[2*k+1]));
            }
            {
                float2 f0 = __half22float2(p0[4]);
                float2 f1 = __half22float2(p1[4]);
                acc[8] = __fmaf_rn(al0, f0.x, __fmaf_rn(al1, f1.x, acc[8]));
            }
        }
#pragma unroll
        for (int l = 0; l < LL; ++l) spart[g][l*HV + d] = acc[l];
    }
    __syncthreads();
    for (int idx = t; idx < LL*HV; idx += 256)
        sagg[idx] = ((spart[0][idx] + spart[1][idx]) + spart[2][idx]) + spart[3][idx];
    __syncthreads();

    for (int idx = t; idx < LL*BBC; idx += 256) {
        int l = idx >> 5, d = idx & 31;
        const float* w = wo + c_L3[l]*HV*BBC;
        float acc = 0.f;
#pragma unroll 8
        for (int c = 0; c < HV; ++c) acc = __fmaf_rn(sagg[l*HV + c], w[c*BBC + d], acc);
        if (l == 0) acc += bo[d];
        sout0[idx] = acc;
    }
    __syncthreads();

    if (t < BBC) {
        float g = 0.f;
        for (int c = 0; c < BBC; ++c) g = __fmaf_rn(sout0[c], wg[c*BBC + t], g);
        g += bg[t];
        sgate[t] = g * (1.0f / (1.0f + expf(-g)));
    }
    __syncthreads();

    for (int idx = t; idx < LL*BBC; idx += 256) {
        int l = idx >> 5, d = idx & 31;
        const float* w = wf + c_L3[l]*BBC*BBC;
        float acc = 0.f;
#pragma unroll 8
        for (int c = 0; c < BBC; ++c) acc = __fmaf_rn(sout0[l*BBC + c], w[c*BBC + d], acc);
        if (l == 0) acc += bf[d];
        float val = sout0[idx] + acc * sgate[d];
        soutf[idx] = val;
        out[OFF_OUT + (size_t)i*LL*BBC + idx] = val;
    }
    __syncthreads();

    if (t < 3) {
        float acc = 0.f;
        for (int c = 0; c < BBC; ++c) acc = __fmaf_rn(soutf[(1+t)*BBC + c], wxca[BBC + c], acc);
        svec[t] = acc;
    }
    if (t == 3) {
        float s = 0.f;
        for (int c = 0; c < BBC; ++c) s = __fmaf_rn(soutf[c], wgate[c], s);
        s += bgate[0];
        sg2 = fmaxf(s, 0.f) + log1pf(expf(-fabsf(s)));
    }
    if (t >= 8 && t < 17) {
        int idx = t - 8;
        int k = idx / 3, m = idx - 3*k;
        float acc = 0.f;
        for (int c = 0; c < BBC; ++c) acc = __fmaf_rn(soutf[(1+k)*BBC + c], wbb[(BBC + c)*NBB + m], acc);
        subb[idx] = acc;
    }
    __syncthreads();

    const int nz = noise[i];
    if (t < 3)
        out[(size_t)i*3 + t] = X[i*3+t] + (nz ? svec[t]*sg2 : 0.f);
    if (t >= 8 && t < 17) {
        int idx = t - 8;
        int m = idx / 3, k = idx - 3*m;
        out[OFF_BB + (size_t)i*9 + idx] = bbr[(size_t)i*9 + idx] + (nz ? subb[k*3 + m] : 0.f);
    }
}

// ---------------- launch ----------------------------------------------------
extern "C" void kernel_launch(void* const* d_in, const int* in_sizes, int n_in,
                              void* d_out, int out_size)
{
    const float* X      = (const float*)d_in[0];
    const float* bbr    = (const float*)d_in[1];
    const float* bbf    = (const float*)d_in[2];
    const int*   batch  = (const int*)d_in[3];
    const int*   xmask  = (const int*)d_in[4];
    const int*   noise  = (const int*)d_in[5];
    const float* w1     = (const float*)d_in[6];
    const float* b1     = (const float*)d_in[7];
    const float* w2     = (const float*)d_in[8];
    const float* b2     = (const float*)d_in[9];
    const float* wv     = (const float*)d_in[10];
    const float* bv     = (const float*)d_in[11];
    const float* wo     = (const float*)d_in[12];
    const float* bo     = (const float*)d_in[13];
    const float* wg     = (const float*)d_in[14];
    const float* bg     = (const float*)d_in[15];
    const float* wf     = (const float*)d_in[16];
    const float* bf     = (const float*)d_in[17];
    const float* wxca   = (const float*)d_in[18];
    const float* wgate  = (const float*)d_in[20];
    const float* bgate  = (const float*)d_in[21];
    const float* wbb    = (const float*)d_in[22];
    float* out = (float*)d_out;

    node_v_kernel<<<NN/NVB, 512>>>(bbf, bbr, noise, wv, bv, w1, b1);
    row_kernel<<<NN, 256>>>(X, batch, xmask);
    edge_kernel<<<NN*EPN/EPB, 256>>>(X, w1, w2, b2);
    agg_kernel<<<NN, 256>>>(X, bbr, noise, wo, bo, wg, bg, wf, bf,
                            wxca, wgate, bgate, wbb, out);
}

// round 11
// speedup vs baseline: 2.2548x; 1.0180x over previous
#include <cuda_runtime.h>
#include <cuda_fp16.h>
#include <math.h>

// ---------------- problem constants ----------------
#define NN    4096
#define KNNK  20
#define LRKK  40
#define EPN   60
#define LL    9
#define SPH   35
#define BBC   32
#define NBB   3
#define HEADS 8
#define HV    64
#define HC    32
#define EPB   64
#define NVB   8

#define OFF_BB  (NN*3)
#define OFF_OUT (NN*3 + NN*9)

struct __align__(16) H2x4 { __half2 a, b, c, d; };

__device__ int     g_src[NN*EPN];
__device__ float   g_logit[NN*EPN*HEADS];
__device__ float   g_inv[NN*SPH];
__device__ H2x4    g_v4[NN*HV];    // v values 0..7 as 4x half2 (16B -> LDG.128)
__device__ __half2 g_v1[NN*HV];    // v value 8 (lo half)
__device__ float   g_hsrc[NN*HC];
__device__ float   g_hdst[NN*HC];
__device__ float4  g_xp[NN];       // [x,y,z,x2]; x2=+inf if x_mask

__constant__ int c_L3[LL] = {0,1,1,1,2,2,2,2,2};

// ---------------- threefry2x32 lr key (JAX partitionable path) --------------
// ASCENDING selection key s = (-ln u) * d2e^1.5  (monotone-equivalent to
// descending logit+gumbel ordering; fp near-tie flips only).
__device__ __forceinline__ float lr_key(unsigned int idx, float d2e) {
    unsigned int x0 = 0u, x1 = idx;
    const unsigned int ks0 = 0u, ks1 = 1u, ks2 = 0x1BD11BDBu;
    x0 += ks0; x1 += ks1;
#define TFR(r) { x0 += x1; x1 = __funnelshift_l(x1, x1, (r)); x1 ^= x0; }
    TFR(13) TFR(15) TFR(26) TFR(6);  x0 += ks1; x1 += ks2 + 1u;
    TFR(17) TFR(29) TFR(16) TFR(24); x0 += ks2; x1 += ks0 + 2u;
    TFR(13) TFR(15) TFR(26) TFR(6);  x0 += ks0; x1 += ks1 + 3u;
    TFR(17) TFR(29) TFR(16) TFR(24); x0 += ks1; x1 += ks2 + 4u;
    TFR(13) TFR(15) TFR(26) TFR(6);  x0 += ks2; x1 += ks0 + 5u;
#undef TFR
    unsigned int bits = x0 ^ x1;
    float u = __uint_as_float((bits >> 9) | 0x3f800000u) - 1.0f;
    u = fmaxf(u, 1.17549435e-38f);
    float w = -__logf(u);
    return w * (d2e * __fsqrt_rn(d2e));
}

// ---------------- kernel 1: node features + V(fp16) + partials + xp ---------
__global__ __launch_bounds__(512) void node_v_kernel(
    const float* __restrict__ bbf, const float* __restrict__ bbr,
    const int* __restrict__ noise, const int* __restrict__ xmask,
    const float* __restrict__ X,
    const float* __restrict__ wv, const float* __restrict__ bv,
    const float* __restrict__ w1, const float* __restrict__ b1)
{
    __shared__ float sWV[3*SPH*HV];
    __shared__ float sW1[2*SPH*HC];
    __shared__ float nf[NVB][LL*SPH];
    const int t = threadIdx.x;
    for (int idx = t; idx < 3*SPH*HV; idx += 512) sWV[idx] = wv[idx];
    for (int idx = t; idx < 2*SPH*HC; idx += 512) sW1[idx] = w1[idx];

    const int g = t >> 6;
    const int tt = t & 63;
    const int i = blockIdx.x*NVB + g;

    for (int idx = tt; idx < LL*SPH; idx += 64) {
        int l = idx / SPH, c = idx - l*SPH;
        float v = 0.f;
        if (c < BBC)                    v = bbf[(i*LL + l)*BBC + c];
        else if (l >= 1 && l <= 3)      v = bbr[(i*NBB + (c-BBC))*3 + (l-1)];
        if (l == 0 && c == SPH-1)       v = noise[i] ? 1.0f : 0.0f;
        nf[g][idx] = v;
    }
    if (tt == 0) {
        float x = X[3*i], y = X[3*i+1], z = X[3*i+2];
        float x2 = __fadd_rn(__fadd_rn(__fmul_rn(x,x),__fmul_rn(y,y)),__fmul_rn(z,z));
        g_xp[i] = make_float4(x, y, z, xmask[i] ? __int_as_float(0x7F800000) : x2);
    }
    __syncthreads();
    if (tt < SPH) g_inv[i*SPH + tt] = nf[g][tt];

    if (tt < HC) {
        float acc = b1[tt];
#pragma unroll 7
        for (int c = 0; c < SPH; ++c) acc = __fmaf_rn(nf[g][c], sW1[c*HC + tt], acc);
        g_hsrc[i*HC + tt] = acc;
    } else {
        int d = tt - HC;
        float acc = 0.f;
#pragma unroll 7
        for (int c = 0; c < SPH; ++c) acc = __fmaf_rn(nf[g][c], sW1[(SPH + c)*HC + d], acc);
        g_hdst[i*HC + d] = acc;
    }

    {
        const int d = tt;
        float va[LL];
#pragma unroll
        for (int l = 0; l < LL; ++l) {
            const float* w = sWV + c_L3[l]*SPH*HV;
            float acc = 0.f;
#pragma unroll 7
            for (int c = 0; c < SPH; ++c) acc = __fmaf_rn(nf[g][l*SPH + c], w[c*HV + d], acc);
            if (l == 0) acc += bv[d];
            va[l] = acc;
        }
        H2x4 v4;
        v4.a = __floats2half2_rn(va[0], va[1]);
        v4.b = __floats2half2_rn(va[2], va[3]);
        v4.c = __floats2half2_rn(va[4], va[5]);
        v4.d = __floats2half2_rn(va[6], va[7]);
        g_v4[(size_t)i*HV + d] = v4;
        g_v1[(size_t)i*HV + d] = __floats2half2_rn(va[8], 0.f);
    }
}

// ---------------- radix-select helpers --------------------------------------
template<bool PRE>
__device__ __forceinline__ uint2 radix_select_k(
    const unsigned* s_key, unsigned (*hist)[256], unsigned* sScan,
    unsigned k, unsigned validMax, int t)
{
    const int lane = t & 31, w = t >> 5;
    unsigned prefix = 0, kk = k;
#pragma unroll
    for (int byte = 3; byte >= 0; --byte) {
        const unsigned maskHi = (byte == 3) ? 0u : (0xFFFFFFFFu << (8*(byte+1)));
        if (!(PRE && byte == 3)) {
#pragma unroll
            for (int c = 0; c < 8; ++c) hist[c][t] = 0;
            __syncthreads();
            for (int j = t; j < NN; j += 256) {
                unsigned u = s_key[j];
                if (u < validMax && (u & maskHi) == prefix)
                    atomicAdd(&hist[w][(u >> (8*byte)) & 255u], 1u);
            }
            __syncthreads();
        }
        unsigned cnt = 0;
#pragma unroll
        for (int c = 0; c < 8; ++c) cnt += hist[c][t];
        unsigned v = cnt;
#pragma unroll
        for (int o = 1; o < 32; o <<= 1) {
            unsigned n = __shfl_up_sync(0xffffffffu, v, o);
            if (lane >= o) v += n;
        }
        if (lane == 31) sScan[w] = v;
        __syncthreads();
        if (t == 0) {
            unsigned a = 0;
#pragma unroll
            for (int c = 0; c < 8; ++c) { unsigned x = sScan[c]; sScan[c] = a; a += x; }
        }
        __syncthreads();
        unsigned incl = v + sScan[w];
        unsigned excl = incl - cnt;
        if (kk > excl && kk <= incl) { sScan[8] = (unsigned)t; sScan[9] = excl; }
        __syncthreads();
        prefix |= sScan[8] << (8*byte);
        kk -= sScan[9];
        __syncthreads();
    }
    return make_uint2(prefix, kk);
}

__device__ __forceinline__ void collect_k(
    const unsigned* s_key, unsigned T, int cLess, int need,
    int* sel, unsigned* sc, int t)
{
    const int lane = t & 31, w = t >> 5;
    const unsigned lm = (1u << lane) - 1u;
    int runL = 0, runE = 0;
    for (int base = 0; base < NN; base += 256) {
        const int j = base + t;
        const unsigned u = s_key[j];
        const bool pL = (u < T);
        const bool pE = (u == T);
        unsigned balL = __ballot_sync(0xffffffffu, pL);
        unsigned balE = __ballot_sync(0xffffffffu, pE);
        if (lane == 0) { sc[w] = __popc(balL); sc[8+w] = __popc(balE); }
        __syncthreads();
        if (t == 0) {
            unsigned a = 0, b = 0;
#pragma unroll
            for (int c = 0; c < 8; ++c) {
                unsigned x = sc[c];   sc[c]   = a; a += x;
                unsigned y = sc[8+c]; sc[8+c] = b; b += y;
            }
            sc[16] = a; sc[17] = b;
        }
        __syncthreads();
        int rL = (int)sc[w]   + __popc(balL & lm);
        int rE = (int)sc[8+w] + __popc(balE & lm);
        if (pL && runL + rL < cLess) sel[runL + rL] = j;
        if (pE && runE + rE < need)  sel[cLess + runE + rE] = j;
        runL += (int)sc[16]; runE += (int)sc[17];
        __syncthreads();
        if (runL >= cLess && runE >= need) break;
    }
}

// ---------------- kernel 2: distances + knn top20 + lr top40 ---------------
__global__ __launch_bounds__(256) void row_kernel(
    const int* __restrict__ xmask)
{
    __shared__ unsigned s_key[NN];
    __shared__ unsigned s_hist[8][256];
    __shared__ unsigned sScan[10];
    __shared__ unsigned sColl[18];
    __shared__ int      sIdx[LRKK];
    const int i = blockIdx.x;
    const int t = threadIdx.x;
    const int w = t >> 5;
    const unsigned U_INV = __float_as_uint(1e30f);

    if (xmask[i] != 0) {
        for (int e = t; e < EPN; e += 256)
            g_src[i*EPN + e] = (e < KNNK) ? e : (e - KNNK);
        return;
    }

    const float4 pi = g_xp[i];
    const float xi = pi.x, yi = pi.y, zi = pi.z, x2i = pi.w;
    const int bi = i >> 11;   // batch = repeat(arange(2), 2048)

    // fill keys + fused byte-3 histogram (masked j carry x2=+inf -> key >= U_INV)
#pragma unroll
    for (int c = 0; c < 8; ++c) s_hist[c][t] = 0;
    __syncthreads();
    for (int j = t; j < NN; j += 256) {
        float4 p = g_xp[j];
        float dot = __fmul_rn(xi, p.x);
        dot = __fmaf_rn(yi, p.y, dot);
        dot = __fmaf_rn(zi, p.z, dot);
        float d2  = fmaxf(__fsub_rn(__fadd_rn(x2i, p.w), __fmul_rn(2.0f, dot)), 0.0f);
        bool invalid = ((j >> 11) != bi) || (j == i);
        unsigned u = invalid ? U_INV : __float_as_uint(d2);  // d2=inf for masked j
        s_key[j] = u;
        if (u < U_INV) atomicAdd(&s_hist[w][u >> 24], 1u);
    }
    __syncthreads();

    uint2 rk = radix_select_k<true>(s_key, s_hist, sScan, KNNK, U_INV, t);
    collect_k(s_key, rk.x, KNNK - (int)rk.y, (int)rk.y, sIdx, sColl, t);
    if (t < KNNK) g_src[i*EPN + t] = sIdx[t];
    if (t < KNNK) s_key[sIdx[t]] = U_INV;
    __syncthreads();

    // lr: ascending key s = (-ln u)*d2e^1.5 ; fused byte-3 histogram
#pragma unroll
    for (int c = 0; c < 8; ++c) s_hist[c][t] = 0;
    __syncthreads();
    for (int j = t; j < NN; j += 256) {
        unsigned u = s_key[j];
        unsigned outk = U_INV;
        if (u < U_INV) {
            float d2e = __fadd_rn(__uint_as_float(u), 1e-6f);
            float s = lr_key((unsigned)(i*NN + j), d2e);
            outk = __float_as_uint(s);
            atomicAdd(&s_hist[w][outk >> 24], 1u);
        }
        s_key[j] = outk;
    }
    __syncthreads();

    rk = radix_select_k<true>(s_key, s_hist, sScan, LRKK, U_INV, t);
    collect_k(s_key, rk.x, LRKK - (int)rk.y, (int)rk.y, sIdx, sColl, t);
    if (t < LRKK) g_src[i*EPN + KNNK + t] = sIdx[t];
}

// ---------------- kernel 3: edge MLP (factorized; 8 edges per warp) ---------
__global__ __launch_bounds__(256) void edge_kernel(
    const float* __restrict__ w1,
    const float* __restrict__ w2, const float* __restrict__ b2)
{
    __shared__ float sW1eT[HC][36];
    __shared__ float sW2T[HEADS][36];
    __shared__ float sB2[HEADS];
    __shared__ float sEF[8][8][40];
    __shared__ float sH[8][8][40];
    const int t = threadIdx.x, lane = t & 31, warp = t >> 5;
    for (int idx = t; idx < HC*32; idx += 256) {
        int h = idx >> 5, c = idx & 31;
        sW1eT[h][c] = w1[(2*SPH + c)*HC + h];
    }
    for (int idx = t; idx < HEADS*32; idx += 256) {
        int h = idx >> 5, c = idx & 31;
        sW2T[h][c] = w2[c*HEADS + h];
    }
    if (t < HEADS) sB2[t] = b2[t];
    __syncthreads();

    const int e0 = blockIdx.x*EPB + warp*8;

    // stage A: edge features (4 lanes per edge)
    {
        const int e = lane >> 2, q = lane & 3;
        const int edge = e0 + e;
        const int ii = edge / EPN;
        const int ss = g_src[edge];
        float4 ps = g_xp[ss], pd = g_xp[ii];
        float dx = ps.x-pd.x, dy = ps.y-pd.y, dz = ps.z-pd.z;
        float dist = sqrtf(__fadd_rn(__fadd_rn(__fmul_rn(dx,dx),__fmul_rn(dy,dy)),__fmul_rn(dz,dz)));
        if (q < 2) {
#pragma unroll
            for (int r = 0; r < 8; ++r) {
                int f = q*8 + r;
                float mu = (float)f * (20.0f/15.0f);
                float zz = (dist - mu) * 0.8f;
                sEF[warp][e][f] = expf(-zz*zz);
            }
        } else {
            float dfl = (float)(ss - ii);
#pragma unroll
            for (int r = 0; r < 4; ++r) {
                int k = (q-2)*4 + r;
                float fr = expf((float)(2*k) * -0.5756462732485114f);
                float sv, cv;
                sincosf(dfl * fr, &sv, &cv);
                sEF[warp][e][16 + k] = cv;
                sEF[warp][e][24 + k] = sv;
            }
        }
    }
    __syncwarp();

    // stage B: hidden units (lane = hidden unit), float4 smem loads
    {
        float h[8];
#pragma unroll
        for (int e = 0; e < 8; ++e) {
            const int edge = e0 + e;
            const int ii = edge / EPN;
            const int ss = g_src[edge];
            h[e] = g_hsrc[ss*HC + lane] + g_hdst[ii*HC + lane];
        }
#pragma unroll
        for (int c4 = 0; c4 < 32; c4 += 4) {
            float4 w4 = *(const float4*)&sW1eT[lane][c4];
#pragma unroll
            for (int e = 0; e < 8; ++e) {
                float4 f4 = *(const float4*)&sEF[warp][e][c4];
                h[e] = __fmaf_rn(f4.x, w4.x, h[e]);
                h[e] = __fmaf_rn(f4.y, w4.y, h[e]);
                h[e] = __fmaf_rn(f4.z, w4.z, h[e]);
                h[e] = __fmaf_rn(f4.w, w4.w, h[e]);
            }
        }
#pragma unroll
        for (int e = 0; e < 8; ++e) {
            float hv = h[e];
            sH[warp][e][lane] = hv * (1.0f / (1.0f + expf(-hv)));
        }
    }
    __syncwarp();

    // stage C: logits; float4 smem loads
    {
        const int e = lane >> 2;
        const int h0 = lane & 3, h1 = h0 + 4;
        float a0 = sB2[h0], a1 = sB2[h1];
#pragma unroll
        for (int c4 = 0; c4 < 32; c4 += 4) {
            float4 hv = *(const float4*)&sH[warp][e][c4];
            float4 wa = *(const float4*)&sW2T[h0][c4];
            float4 wb = *(const float4*)&sW2T[h1][c4];
            a0 = __fmaf_rn(hv.x, wa.x, a0); a1 = __fmaf_rn(hv.x, wb.x, a1);
            a0 = __fmaf_rn(hv.y, wa.y, a0); a1 = __fmaf_rn(hv.y, wb.y, a1);
            a0 = __fmaf_rn(hv.z, wa.z, a0); a1 = __fmaf_rn(hv.z, wb.z, a1);
            a0 = __fmaf_rn(hv.w, wa.w, a0); a1 = __fmaf_rn(hv.w, wb.w, a1);
        }
        g_logit[(e0+e)*HEADS + h0] = a0;
        g_logit[(e0+e)*HEADS + h1] = a1;
    }
}

// ---------------- kernel 4: softmax + aggregate + epilogues -----------------
__global__ __launch_bounds__(256) void agg_kernel(
    const float* __restrict__ X, const float* __restrict__ bbr,
    const int* __restrict__ noise,
    const float* __restrict__ wo,   const float* __restrict__ bo,
    const float* __restrict__ wg,   const float* __restrict__ bg,
    const float* __restrict__ wf,   const float* __restrict__ bf,
    const float* __restrict__ wxca,
    const float* __restrict__ wgate, const float* __restrict__ bgate,
    const float* __restrict__ wbb,
    float* __restrict__ out)
{
    __shared__ float sal[EPN*HEADS];
    __shared__ int   ssrc[EPN];
    __shared__ float spart[4][LL*HV];
    __shared__ float sagg[LL*HV];
    __shared__ float sout0[LL*BBC];
    __shared__ float soutf[LL*BBC];
    __shared__ float sgate[BBC];
    __shared__ float svec[3];
    __shared__ float sg2;
    __shared__ float subb[9];
    const int i = blockIdx.x;
    const int t = threadIdx.x;

    for (int idx = t; idx < EPN*HEADS; idx += 256) sal[idx] = g_logit[i*EPN*HEADS + idx];
    if (t < EPN) ssrc[t] = g_src[i*EPN + t];
    __syncthreads();

    if (t < 64) {
        const int h = t >> 3, sub = t & 7;
        float m = -3.4e38f;
        for (int e = sub; e < EPN; e += 8) m = fmaxf(m, sal[e*HEADS + h]);
#pragma unroll
        for (int o = 1; o < 8; o <<= 1) m = fmaxf(m, __shfl_xor_sync(0xffffffffu, m, o, 8));
        float Z = 0.f;
        for (int e = sub; e < EPN; e += 8) {
            float pp = expf(sal[e*HEADS + h] - m);
            sal[e*HEADS + h] = pp;
            Z += pp;
        }
#pragma unroll
        for (int o = 1; o < 8; o <<= 1) Z += __shfl_xor_sync(0xffffffffu, Z, o, 8);
        float inv = 1.0f / (Z + 1e-9f);
        for (int e = sub; e < EPN; e += 8) sal[e*HEADS + h] *= inv;
    }
    __syncthreads();

    // gather-aggregate from fp16 v: LDG.128 + LDG.32 per edge pointer
    {
        const int d = t & 63, g = t >> 6;
        float acc[LL];
#pragma unroll
        for (int l = 0; l < LL; ++l) acc[l] = 0.f;
        const int h = d >> 3;
        for (int e = g; e < EPN; e += 8) {
            const int e2 = e + 4;
            const bool has2 = (e2 < EPN);
            int s0 = ssrc[e];
            int s1 = has2 ? ssrc[e2] : s0;
            float al0 = sal[e*HEADS + h];
            float al1 = has2 ? sal[e2*HEADS + h] : 0.f;
            H2x4 a4 = g_v4[(size_t)s0*HV + d];
            H2x4 b4 = g_v4[(size_t)s1*HV + d];
            __half2 a1h = g_v1[(size_t)s0*HV + d];
            __half2 b1h = g_v1[(size_t)s1*HV + d];
#define ACC2(k, ha, hb) { \
            float2 fa = __half22float2(ha); \
            float2 fb = __half22float2(hb); \
            acc[2*(k)]   = __fmaf_rn(al0, fa.x, __fmaf_rn(al1, fb.x, acc[2*(k)])); \
            acc[2*(k)+1] = __fmaf_rn(al0, fa.y, __fmaf_rn(al1, fb.y, acc[2*(k)+1])); }
            ACC2(0, a4.a, b4.a)
            ACC2(1, a4.b, b4.b)
            ACC2(2, a4.c, b4.c)
            ACC2(3, a4.d, b4.d)
#undef ACC2
            {
                float2 fa = __half22float2(a1h);
                float2 fb = __half22float2(b1h);
                acc[8] = __fmaf_rn(al0, fa.x, __fmaf_rn(al1, fb.x, acc[8]));
            }
        }
#pragma unroll
        for (int l = 0; l < LL; ++l) spart[g][l*HV + d] = acc[l];
    }
    __syncthreads();
    for (int idx = t; idx < LL*HV; idx += 256)
        sagg[idx] = ((spart[0][idx] + spart[1][idx]) + spart[2][idx]) + spart[3][idx];
    __syncthreads();

    for (int idx = t; idx < LL*BBC; idx += 256) {
        int l = idx >> 5, d = idx & 31;
        const float* w = wo + c_L3[l]*HV*BBC;
        float acc = 0.f;
#pragma unroll 8
        for (int c = 0; c < HV; ++c) acc = __fmaf_rn(sagg[l*HV + c], w[c*BBC + d], acc);
        if (l == 0) acc += bo[d];
        sout0[idx] = acc;
    }
    __syncthreads();

    if (t < BBC) {
        float g = 0.f;
        for (int c = 0; c < BBC; ++c) g = __fmaf_rn(sout0[c], wg[c*BBC + t], g);
        g += bg[t];
        sgate[t] = g * (1.0f / (1.0f + expf(-g)));
    }
    __syncthreads();

    for (int idx = t; idx < LL*BBC; idx += 256) {
        int l = idx >> 5, d = idx & 31;
        const float* w = wf + c_L3[l]*BBC*BBC;
        float acc = 0.f;
#pragma unroll 8
        for (int c = 0; c < BBC; ++c) acc = __fmaf_rn(sout0[l*BBC + c], w[c*BBC + d], acc);
        if (l == 0) acc += bf[d];
        float val = sout0[idx] + acc * sgate[d];
        soutf[idx] = val;
        out[OFF_OUT + (size_t)i*LL*BBC + idx] = val;
    }
    __syncthreads();

    if (t < 3) {
        float acc = 0.f;
        for (int c = 0; c < BBC; ++c) acc = __fmaf_rn(soutf[(1+t)*BBC + c], wxca[BBC + c], acc);
        svec[t] = acc;
    }
    if (t == 3) {
        float s = 0.f;
        for (int c = 0; c < BBC; ++c) s = __fmaf_rn(soutf[c], wgate[c], s);
        s += bgate[0];
        sg2 = fmaxf(s, 0.f) + log1pf(expf(-fabsf(s)));
    }
    if (t >= 8 && t < 17) {
        int idx = t - 8;
        int k = idx / 3, m = idx - 3*k;
        float acc = 0.f;
        for (int c = 0; c < BBC; ++c) acc = __fmaf_rn(soutf[(1+k)*BBC + c], wbb[(BBC + c)*NBB + m], acc);
        subb[idx] = acc;
    }
    __syncthreads();

    const int nz = noise[i];
    if (t < 3)
        out[(size_t)i*3 + t] = X[i*3+t] + (nz ? svec[t]*sg2 : 0.f);
    if (t >= 8 && t < 17) {
        int idx = t - 8;
        int m = idx / 3, k = idx - 3*m;
        out[OFF_BB + (size_t)i*9 + idx] = bbr[(size_t)i*9 + idx] + (nz ? subb[k*3 + m] : 0.f);
    }
}

// ---------------- launch ----------------------------------------------------
extern "C" void kernel_launch(void* const* d_in, const int* in_sizes, int n_in,
                              void* d_out, int out_size)
{
    const float* X      = (const float*)d_in[0];
    const float* bbr    = (const float*)d_in[1];
    const float* bbf    = (const float*)d_in[2];
    const int*   xmask  = (const int*)d_in[4];
    const int*   noise  = (const int*)d_in[5];
    const float* w1     = (const float*)d_in[6];
    const float* b1     = (const float*)d_in[7];
    const float* w2     = (const float*)d_in[8];
    const float* b2     = (const float*)d_in[9];
    const float* wv     = (const float*)d_in[10];
    const float* bv     = (const float*)d_in[11];
    const float* wo     = (const float*)d_in[12];
    const float* bo     = (const float*)d_in[13];
    const float* wg     = (const float*)d_in[14];
    const float* bg     = (const float*)d_in[15];
    const float* wf     = (const float*)d_in[16];
    const float* bf     = (const float*)d_in[17];
    const float* wxca   = (const float*)d_in[18];
    const float* wgate  = (const float*)d_in[20];
    const float* bgate  = (const float*)d_in[21];
    const float* wbb    = (const float*)d_in[22];
    float* out = (float*)d_out;

    node_v_kernel<<<NN/NVB, 512>>>(bbf, bbr, noise, xmask, X, wv, bv, w1, b1);
    row_kernel<<<NN, 256>>>(xmask);
    edge_kernel<<<NN*EPN/EPB, 256>>>(w1, w2, b2);
    agg_kernel<<<NN, 256>>>(X, bbr, noise, wo, bo, wg, bg, wf, bf,
                            wxca, wgate, bgate, wbb, out);
}

// round 12
// speedup vs baseline: 2.4957x; 1.1069x over previous
#include <cuda_runtime.h>
#include <cuda_fp16.h>
#include <math.h>

// ---------------- problem constants ----------------
#define NN    4096
#define KNNK  20
#define LRKK  40
#define EPN   60
#define LL    9
#define SPH   35
#define BBC   32
#define NBB   3
#define HEADS 8
#define HV    64
#define HC    32
#define EPB   64
#define NVB   8
#define CAP   3072

#define OFF_BB  (NN*3)
#define OFF_OUT (NN*3 + NN*9)

__device__ int     g_src[NN*EPN];
__device__ float   g_logit[NN*EPN*HEADS];
__device__ float   g_inv[NN*SPH];
__device__ __half2 g_vh[NN*HV*5];   // [node][d][5 half2] = 9 v-values + pad
__device__ float   g_hsrc[NN*HC];
__device__ float   g_hdst[NN*HC];
__device__ float4  g_xp[NN];        // [x,y,z,x2]; x2=+inf if x_mask

__constant__ int c_L3[LL] = {0,1,1,1,2,2,2,2,2};

// ---------------- threefry2x32 lr key (JAX partitionable path) --------------
// ASCENDING selection key s = (-ln u) * d2e^1.5 (monotone-equiv to gumbel logit)
__device__ __forceinline__ float lr_key(unsigned int idx, float d2e) {
    unsigned int x0 = 0u, x1 = idx;
    const unsigned int ks0 = 0u, ks1 = 1u, ks2 = 0x1BD11BDBu;
    x0 += ks0; x1 += ks1;
#define TFR(r) { x0 += x1; x1 = __funnelshift_l(x1, x1, (r)); x1 ^= x0; }
    TFR(13) TFR(15) TFR(26) TFR(6);  x0 += ks1; x1 += ks2 + 1u;
    TFR(17) TFR(29) TFR(16) TFR(24); x0 += ks2; x1 += ks0 + 2u;
    TFR(13) TFR(15) TFR(26) TFR(6);  x0 += ks0; x1 += ks1 + 3u;
    TFR(17) TFR(29) TFR(16) TFR(24); x0 += ks1; x1 += ks2 + 4u;
    TFR(13) TFR(15) TFR(26) TFR(6);  x0 += ks2; x1 += ks0 + 5u;
#undef TFR
    unsigned int bits = x0 ^ x1;
    float u = __uint_as_float((bits >> 9) | 0x3f800000u) - 1.0f;
    u = fmaxf(u, 1.17549435e-38f);
    float w = -__logf(u);
    return w * (d2e * __fsqrt_rn(d2e));
}

// ---------------- kernel 1: node features + V(fp16) + partials + xp ---------
__global__ __launch_bounds__(512) void node_v_kernel(
    const float* __restrict__ bbf, const float* __restrict__ bbr,
    const int* __restrict__ noise, const int* __restrict__ xmask,
    const float* __restrict__ X,
    const float* __restrict__ wv, const float* __restrict__ bv,
    const float* __restrict__ w1, const float* __restrict__ b1)
{
    __shared__ float sWV[3*SPH*HV];
    __shared__ float sW1[2*SPH*HC];
    __shared__ float nf[NVB][LL*SPH];
    const int t = threadIdx.x;
    for (int idx = t; idx < 3*SPH*HV; idx += 512) sWV[idx] = wv[idx];
    for (int idx = t; idx < 2*SPH*HC; idx += 512) sW1[idx] = w1[idx];

    const int g = t >> 6;
    const int tt = t & 63;
    const int i = blockIdx.x*NVB + g;

    for (int idx = tt; idx < LL*SPH; idx += 64) {
        int l = idx / SPH, c = idx - l*SPH;
        float v = 0.f;
        if (c < BBC)                    v = bbf[(i*LL + l)*BBC + c];
        else if (l >= 1 && l <= 3)      v = bbr[(i*NBB + (c-BBC))*3 + (l-1)];
        if (l == 0 && c == SPH-1)       v = noise[i] ? 1.0f : 0.0f;
        nf[g][idx] = v;
    }
    if (tt == 0) {
        float x = X[3*i], y = X[3*i+1], z = X[3*i+2];
        float x2 = __fadd_rn(__fadd_rn(__fmul_rn(x,x),__fmul_rn(y,y)),__fmul_rn(z,z));
        g_xp[i] = make_float4(x, y, z, xmask[i] ? __int_as_float(0x7F800000) : x2);
    }
    __syncthreads();
    if (tt < SPH) g_inv[i*SPH + tt] = nf[g][tt];

    if (tt < HC) {
        float acc = b1[tt];
#pragma unroll 7
        for (int c = 0; c < SPH; ++c) acc = __fmaf_rn(nf[g][c], sW1[c*HC + tt], acc);
        g_hsrc[i*HC + tt] = acc;
    } else {
        int d = tt - HC;
        float acc = 0.f;
#pragma unroll 7
        for (int c = 0; c < SPH; ++c) acc = __fmaf_rn(nf[g][c], sW1[(SPH + c)*HC + d], acc);
        g_hdst[i*HC + d] = acc;
    }

    {
        const int d = tt;
        float va[LL];
#pragma unroll
        for (int l = 0; l < LL; ++l) {
            const float* w = sWV + c_L3[l]*SPH*HV;
            float acc = 0.f;
#pragma unroll 7
            for (int c = 0; c < SPH; ++c) acc = __fmaf_rn(nf[g][l*SPH + c], w[c*HV + d], acc);
            if (l == 0) acc += bv[d];
            va[l] = acc;
        }
        __half2* dst = g_vh + ((size_t)i*HV + d)*5;
        dst[0] = __floats2half2_rn(va[0], va[1]);
        dst[1] = __floats2half2_rn(va[2], va[3]);
        dst[2] = __floats2half2_rn(va[4], va[5]);
        dst[3] = __floats2half2_rn(va[6], va[7]);
        dst[4] = __floats2half2_rn(va[8], 0.f);
    }
}

// ---------------- radix-select with candidate compaction --------------------
// PICK: all-thread bin selection from hist into (prefix, kk). Leaves results
// uniform in registers via sScan[8]/sScan[9].
#define PICK(BYTE)                                                             \
    {                                                                          \
        unsigned cnt = 0;                                                      \
        _Pragma("unroll")                                                      \
        for (int c = 0; c < 8; ++c) cnt += hist[c][t];                         \
        unsigned v = cnt;                                                      \
        _Pragma("unroll")                                                      \
        for (int o = 1; o < 32; o <<= 1) {                                     \
            unsigned n = __shfl_up_sync(0xffffffffu, v, o);                    \
            if (lane >= o) v += n;                                             \
        }                                                                      \
        if (lane == 31) sScan[w] = v;                                          \
        __syncthreads();                                                       \
        if (t == 0) {                                                          \
            unsigned a = 0;                                                    \
            _Pragma("unroll")                                                  \
            for (int c = 0; c < 8; ++c) { unsigned x = sScan[c]; sScan[c] = a; a += x; } \
        }                                                                      \
        __syncthreads();                                                       \
        unsigned incl = v + sScan[w];                                          \
        unsigned excl = incl - cnt;                                            \
        if (kk > excl && kk <= incl) { sScan[8] = (unsigned)t; sScan[9] = excl; } \
        __syncthreads();                                                       \
        prefix |= sScan[8] << (8*(BYTE));                                      \
        kk -= sScan[9];                                                        \
        __syncthreads();                                                       \
    }

// Find k-th smallest among keys < validMax. Byte-3 histogram must be pre-built.
__device__ __forceinline__ uint2 radix_select(
    const unsigned* s_key, unsigned (*hist)[256], unsigned* sScan,
    unsigned short* cand, unsigned* sCnt,
    unsigned k, unsigned validMax, int t)
{
    const int lane = t & 31, w = t >> 5;
    unsigned prefix = 0, kk = k;

    PICK(3)

    // compact candidates sharing the selected byte-3 bin
    if (t == 0) sCnt[0] = 0;
    __syncthreads();
    const unsigned b3 = prefix >> 24;
    for (int j = t; j < NN; j += 256) {
        unsigned u = s_key[j];
        if (u < validMax && (u >> 24) == b3) {
            unsigned p = atomicAdd(&sCnt[0], 1u);
            if (p < CAP) cand[p] = (unsigned short)j;
        }
    }
    __syncthreads();
    const int candN = (int)sCnt[0];
    const bool useCand = (candN <= CAP);

#pragma unroll
    for (int byte = 2; byte >= 0; --byte) {
        const unsigned maskHi = 0xFFFFFFFFu << (8*(byte+1));
#pragma unroll
        for (int c = 0; c < 8; ++c) hist[c][t] = 0;
        __syncthreads();
        if (useCand) {
            for (int c = t; c < candN; c += 256) {
                unsigned u = s_key[cand[c]];
                if ((u & maskHi) == prefix)
                    atomicAdd(&hist[w][(u >> (8*byte)) & 255u], 1u);
            }
        } else {
            for (int j = t; j < NN; j += 256) {
                unsigned u = s_key[j];
                if (u < validMax && (u & maskHi) == prefix)
                    atomicAdd(&hist[w][(u >> (8*byte)) & 255u], 1u);
            }
        }
        __syncthreads();
        PICK(byte)
    }
    return make_uint2(prefix, kk);
}

// ---------------- kernel 2: distances + knn top20 + lr top40 ---------------
__global__ __launch_bounds__(256) void row_kernel(
    const int* __restrict__ xmask)
{
    __shared__ unsigned s_key[NN];           // 16 KB
    __shared__ unsigned s_hist[8][256];      // 8 KB
    __shared__ unsigned sScan[10];
    __shared__ unsigned short sCand[CAP];    // 6 KB
    __shared__ unsigned sCnt[4];             // [0] candN, [1] cntL, [2] cntE
    __shared__ int      sSel[EPN];
    __shared__ int      sTie[64];
    const int i = blockIdx.x;
    const int t = threadIdx.x;
    const int w = t >> 5;
    const unsigned U_INV = __float_as_uint(1e30f);

    if (xmask[i] != 0) {
        for (int e = t; e < EPN; e += 256)
            g_src[i*EPN + e] = (e < KNNK) ? e : (e - KNNK);
        return;
    }

    const float4 pi = g_xp[i];
    const float xi = pi.x, yi = pi.y, zi = pi.z, x2i = pi.w;
    const int bi = i >> 11;   // batch = repeat(arange(2), 2048)

    // ---- fill keys + fused byte-3 histogram
#pragma unroll
    for (int c = 0; c < 8; ++c) s_hist[c][t] = 0;
    __syncthreads();
    for (int j = t; j < NN; j += 256) {
        float4 p = g_xp[j];
        float dot = __fmul_rn(xi, p.x);
        dot = __fmaf_rn(yi, p.y, dot);
        dot = __fmaf_rn(zi, p.z, dot);
        float d2  = fmaxf(__fsub_rn(__fadd_rn(x2i, p.w), __fmul_rn(2.0f, dot)), 0.0f);
        bool invalid = ((j >> 11) != bi) || (j == i);
        unsigned u = invalid ? U_INV : __float_as_uint(d2);  // d2=inf for masked j
        s_key[j] = u;
        if (u < U_INV) atomicAdd(&s_hist[w][u >> 24], 1u);
    }
    __syncthreads();

    // ================= knn stage =================
    {
        uint2 rk = radix_select(s_key, s_hist, sScan, sCand, sCnt, KNNK, U_INV, t);
        const unsigned T = rk.x;
        const int need = (int)rk.y;
        const int cLess = KNNK - need;

        if (t == 0) { sCnt[1] = 0; sCnt[2] = 0; }
        __syncthreads();
        for (int j = t; j < NN; j += 256) {
            unsigned u = s_key[j];
            if (u < T) {
                int p = (int)atomicAdd(&sCnt[1], 1u);
                sSel[p] = j;
            } else if (u == T) {
                int p = (int)atomicAdd(&sCnt[2], 1u);
                if (p < 64) sTie[p] = j;
            }
        }
        __syncthreads();
        if (t == 0) {  // lowest-index ties (JAX stable top_k)
            int nt = min((int)sCnt[2], 64);
            int last = -1;
            for (int r = 0; r < need; ++r) {
                int best = 0x7FFFFFFF;
                for (int q = 0; q < nt; ++q) { int j = sTie[q]; if (j > last && j < best) best = j; }
                sSel[cLess + r] = best;
                last = best;
            }
        }
        __syncthreads();
        if (t < KNNK) {   // deterministic ascending-index order + mark selected
            int myj = sSel[t];
            int rank = 0;
#pragma unroll 4
            for (int q = 0; q < KNNK; ++q) rank += (sSel[q] < myj);
            g_src[i*EPN + rank] = myj;
            s_key[myj] = U_INV;
        }
        __syncthreads();
    }

    // ---- lr transform: ascending key (-ln u)*d2e^1.5 + fused byte-3 hist
#pragma unroll
    for (int c = 0; c < 8; ++c) s_hist[c][t] = 0;
    __syncthreads();
    for (int j = t; j < NN; j += 256) {
        unsigned u = s_key[j];
        unsigned outk = U_INV;
        if (u < U_INV) {
            float d2e = __fadd_rn(__uint_as_float(u), 1e-6f);
            float s = lr_key((unsigned)(i*NN + j), d2e);
            outk = __float_as_uint(s);
            atomicAdd(&s_hist[w][outk >> 24], 1u);
        }
        s_key[j] = outk;
    }
    __syncthreads();

    // ================= lr stage =================
    {
        uint2 rk = radix_select(s_key, s_hist, sScan, sCand, sCnt, LRKK, U_INV, t);
        const unsigned T = rk.x;
        const int need = (int)rk.y;
        const int cLess = LRKK - need;

        if (t == 0) { sCnt[1] = 0; sCnt[2] = 0; }
        __syncthreads();
        for (int j = t; j < NN; j += 256) {
            unsigned u = s_key[j];
            if (u < T) {
                int p = (int)atomicAdd(&sCnt[1], 1u);
                sSel[p] = j;
            } else if (u == T) {
                int p = (int)atomicAdd(&sCnt[2], 1u);
                if (p < 64) sTie[p] = j;
            }
        }
        __syncthreads();
        if (t == 0) {
            int nt = min((int)sCnt[2], 64);
            int last = -1;
            for (int r = 0; r < need; ++r) {
                int best = 0x7FFFFFFF;
                for (int q = 0; q < nt; ++q) { int j = sTie[q]; if (j > last && j < best) best = j; }
                sSel[cLess + r] = best;
                last = best;
            }
        }
        __syncthreads();
        if (t < LRKK) {
            int myj = sSel[t];
            int rank = 0;
#pragma unroll 4
            for (int q = 0; q < LRKK; ++q) rank += (sSel[q] < myj);
            g_src[i*EPN + KNNK + rank] = myj;
        }
    }
}

// ---------------- kernel 3: edge MLP (factorized; 8 edges per warp) ---------
__global__ __launch_bounds__(256) void edge_kernel(
    const float* __restrict__ w1,
    const float* __restrict__ w2, const float* __restrict__ b2)
{
    __shared__ float sW1eT[HC][36];
    __shared__ float sW2T[HEADS][36];
    __shared__ float sB2[HEADS];
    __shared__ float sEF[8][8][40];
    __shared__ float sH[8][8][40];
    const int t = threadIdx.x, lane = t & 31, warp = t >> 5;
    for (int idx = t; idx < HC*32; idx += 256) {
        int h = idx >> 5, c = idx & 31;
        sW1eT[h][c] = w1[(2*SPH + c)*HC + h];
    }
    for (int idx = t; idx < HEADS*32; idx += 256) {
        int h = idx >> 5, c = idx & 31;
        sW2T[h][c] = w2[c*HEADS + h];
    }
    if (t < HEADS) sB2[t] = b2[t];
    __syncthreads();

    const int e0 = blockIdx.x*EPB + warp*8;

    {
        const int e = lane >> 2, q = lane & 3;
        const int edge = e0 + e;
        const int ii = edge / EPN;
        const int ss = g_src[edge];
        float4 ps = g_xp[ss], pd = g_xp[ii];
        float dx = ps.x-pd.x, dy = ps.y-pd.y, dz = ps.z-pd.z;
        float dist = sqrtf(__fadd_rn(__fadd_rn(__fmul_rn(dx,dx),__fmul_rn(dy,dy)),__fmul_rn(dz,dz)));
        if (q < 2) {
#pragma unroll
            for (int r = 0; r < 8; ++r) {
                int f = q*8 + r;
                float mu = (float)f * (20.0f/15.0f);
                float zz = (dist - mu) * 0.8f;
                sEF[warp][e][f] = expf(-zz*zz);
            }
        } else {
            float dfl = (float)(ss - ii);
#pragma unroll
            for (int r = 0; r < 4; ++r) {
                int k = (q-2)*4 + r;
                float fr = expf((float)(2*k) * -0.5756462732485114f);
                float sv, cv;
                sincosf(dfl * fr, &sv, &cv);
                sEF[warp][e][16 + k] = cv;
                sEF[warp][e][24 + k] = sv;
            }
        }
    }
    __syncwarp();

    {
        float h[8];
#pragma unroll
        for (int e = 0; e < 8; ++e) {
            const int edge = e0 + e;
            const int ii = edge / EPN;
            const int ss = g_src[edge];
            h[e] = g_hsrc[ss*HC + lane] + g_hdst[ii*HC + lane];
        }
#pragma unroll
        for (int c4 = 0; c4 < 32; c4 += 4) {
            float4 w4 = *(const float4*)&sW1eT[lane][c4];
#pragma unroll
            for (int e = 0; e < 8; ++e) {
                float4 f4 = *(const float4*)&sEF[warp][e][c4];
                h[e] = __fmaf_rn(f4.x, w4.x, h[e]);
                h[e] = __fmaf_rn(f4.y, w4.y, h[e]);
                h[e] = __fmaf_rn(f4.z, w4.z, h[e]);
                h[e] = __fmaf_rn(f4.w, w4.w, h[e]);
            }
        }
#pragma unroll
        for (int e = 0; e < 8; ++e) {
            float hv = h[e];
            sH[warp][e][lane] = hv * (1.0f / (1.0f + expf(-hv)));
        }
    }
    __syncwarp();

    {
        const int e = lane >> 2;
        const int h0 = lane & 3, h1 = h0 + 4;
        float a0 = sB2[h0], a1 = sB2[h1];
#pragma unroll
        for (int c4 = 0; c4 < 32; c4 += 4) {
            float4 hv = *(const float4*)&sH[warp][e][c4];
            float4 wa = *(const float4*)&sW2T[h0][c4];
            float4 wb = *(const float4*)&sW2T[h1][c4];
            a0 = __fmaf_rn(hv.x, wa.x, a0); a1 = __fmaf_rn(hv.x, wb.x, a1);
            a0 = __fmaf_rn(hv.y, wa.y, a0); a1 = __fmaf_rn(hv.y, wb.y, a1);
            a0 = __fmaf_rn(hv.z, wa.z, a0); a1 = __fmaf_rn(hv.z, wb.z, a1);
            a0 = __fmaf_rn(hv.w, wa.w, a0); a1 = __fmaf_rn(hv.w, wb.w, a1);
        }
        g_logit[(e0+e)*HEADS + h0] = a0;
        g_logit[(e0+e)*HEADS + h1] = a1;
    }
}

// ---------------- kernel 4: softmax + aggregate + epilogues -----------------
__global__ __launch_bounds__(256) void agg_kernel(
    const float* __restrict__ X, const float* __restrict__ bbr,
    const int* __restrict__ noise,
    const float* __restrict__ wo,   const float* __restrict__ bo,
    const float* __restrict__ wg,   const float* __restrict__ bg,
    const float* __restrict__ wf,   const float* __restrict__ bf,
    const float* __restrict__ wxca,
    const float* __restrict__ wgate, const float* __restrict__ bgate,
    const float* __restrict__ wbb,
    float* __restrict__ out)
{
    __shared__ float sal[EPN*HEADS];
    __shared__ int   ssrc[EPN];
    __shared__ float spart[4][LL*HV];
    __shared__ float sagg[LL*HV];
    __shared__ float sout0[LL*BBC];
    __shared__ float soutf[LL*BBC];
    __shared__ float sgate[BBC];
    __shared__ float svec[3];
    __shared__ float sg2;
    __shared__ float subb[9];
    const int i = blockIdx.x;
    const int t = threadIdx.x;

    for (int idx = t; idx < EPN*HEADS; idx += 256) sal[idx] = g_logit[i*EPN*HEADS + idx];
    if (t < EPN) ssrc[t] = g_src[i*EPN + t];
    __syncthreads();

    if (t < 64) {
        const int h = t >> 3, sub = t & 7;
        float m = -3.4e38f;
        for (int e = sub; e < EPN; e += 8) m = fmaxf(m, sal[e*HEADS + h]);
#pragma unroll
        for (int o = 1; o < 8; o <<= 1) m = fmaxf(m, __shfl_xor_sync(0xffffffffu, m, o, 8));
        float Z = 0.f;
        for (int e = sub; e < EPN; e += 8) {
            float pp = expf(sal[e*HEADS + h] - m);
            sal[e*HEADS + h] = pp;
            Z += pp;
        }
#pragma unroll
        for (int o = 1; o < 8; o <<= 1) Z += __shfl_xor_sync(0xffffffffu, Z, o, 8);
        float inv = 1.0f / (Z + 1e-9f);
        for (int e = sub; e < EPN; e += 8) sal[e*HEADS + h] *= inv;
    }
    __syncthreads();

    // gather-aggregate from fp16 v (R9-proven form: 5x half2, 2-edge unroll)
    {
        const int d = t & 63, g = t >> 6;
        float acc[LL];
#pragma unroll
        for (int l = 0; l < LL; ++l) acc[l] = 0.f;
        const int h = d >> 3;
        for (int e = g; e < EPN; e += 8) {
            const int e2 = e + 4;
            const bool has2 = (e2 < EPN);
            int s0 = ssrc[e];
            int s1 = has2 ? ssrc[e2] : s0;
            float al0 = sal[e*HEADS + h];
            float al1 = has2 ? sal[e2*HEADS + h] : 0.f;
            const __half2* p0 = g_vh + ((size_t)s0*HV + d)*5;
            const __half2* p1 = g_vh + ((size_t)s1*HV + d)*5;
#pragma unroll
            for (int k = 0; k < 4; ++k) {
                float2 f0 = __half22float2(p0[k]);
                float2 f1 = __half22float2(p1[k]);
                acc[2*k]   = __fmaf_rn(al0, f0.x, __fmaf_rn(al1, f1.x, acc[2*k]));
                acc[2*k+1] = __fmaf_rn(al0, f0.y, __fmaf_rn(al1, f1.y, acc[2*k+1]));
            }
            {
                float2 f0 = __half22float2(p0[4]);
                float2 f1 = __half22float2(p1[4]);
                acc[8] = __fmaf_rn(al0, f0.x, __fmaf_rn(al1, f1.x, acc[8]));
            }
        }
#pragma unroll
        for (int l = 0; l < LL; ++l) spart[g][l*HV + d] = acc[l];
    }
    __syncthreads();
    for (int idx = t; idx < LL*HV; idx += 256)
        sagg[idx] = ((spart[0][idx] + spart[1][idx]) + spart[2][idx]) + spart[3][idx];
    __syncthreads();

    for (int idx = t; idx < LL*BBC; idx += 256) {
        int l = idx >> 5, d = idx & 31;
        const float* w = wo + c_L3[l]*HV*BBC;
        float acc = 0.f;
#pragma unroll 8
        for (int c = 0; c < HV; ++c) acc = __fmaf_rn(sagg[l*HV + c], w[c*BBC + d], acc);
        if (l == 0) acc += bo[d];
        sout0[idx] = acc;
    }
    __syncthreads();

    if (t < BBC) {
        float g = 0.f;
        for (int c = 0; c < BBC; ++c) g = __fmaf_rn(sout0[c], wg[c*BBC + t], g);
        g += bg[t];
        sgate[t] = g * (1.0f / (1.0f + expf(-g)));
    }
    __syncthreads();

    for (int idx = t; idx < LL*BBC; idx += 256) {
        int l = idx >> 5, d = idx & 31;
        const float* w = wf + c_L3[l]*BBC*BBC;
        float acc = 0.f;
#pragma unroll 8
        for (int c = 0; c < BBC; ++c) acc = __fmaf_rn(sout0[l*BBC + c], w[c*BBC + d], acc);
        if (l == 0) acc += bf[d];
        float val = sout0[idx] + acc * sgate[d];
        soutf[idx] = val;
        out[OFF_OUT + (size_t)i*LL*BBC + idx] = val;
    }
    __syncthreads();

    if (t < 3) {
        float acc = 0.f;
        for (int c = 0; c < BBC; ++c) acc = __fmaf_rn(soutf[(1+t)*BBC + c], wxca[BBC + c], acc);
        svec[t] = acc;
    }
    if (t == 3) {
        float s = 0.f;
        for (int c = 0; c < BBC; ++c) s = __fmaf_rn(soutf[c], wgate[c], s);
        s += bgate[0];
        sg2 = fmaxf(s, 0.f) + log1pf(expf(-fabsf(s)));
    }
    if (t >= 8 && t < 17) {
        int idx = t - 8;
        int k = idx / 3, m = idx - 3*k;
        float acc = 0.f;
        for (int c = 0; c < BBC; ++c) acc = __fmaf_rn(soutf[(1+k)*BBC + c], wbb[(BBC + c)*NBB + m], acc);
        subb[idx] = acc;
    }
    __syncthreads();

    const int nz = noise[i];
    if (t < 3)
        out[(size_t)i*3 + t] = X[i*3+t] + (nz ? svec[t]*sg2 : 0.f);
    if (t >= 8 && t < 17) {
        int idx = t - 8;
        int m = idx / 3, k = idx - 3*m;
        out[OFF_BB + (size_t)i*9 + idx] = bbr[(size_t)i*9 + idx] + (nz ? subb[k*3 + m] : 0.f);
    }
}

// ---------------- launch ----------------------------------------------------
extern "C" void kernel_launch(void* const* d_in, const int* in_sizes, int n_in,
                              void* d_out, int out_size)
{
    const float* X      = (const float*)d_in[0];
    const float* bbr    = (const float*)d_in[1];
    const float* bbf    = (const float*)d_in[2];
    const int*   xmask  = (const int*)d_in[4];
    const int*   noise  = (const int*)d_in[5];
    const float* w1     = (const float*)d_in[6];
    const float* b1     = (const float*)d_in[7];
    const float* w2     = (const float*)d_in[8];
    const float* b2     = (const float*)d_in[9];
    const float* wv     = (const float*)d_in[10];
    const float* bv     = (const float*)d_in[11];
    const float* wo     = (const float*)d_in[12];
    const float* bo     = (const float*)d_in[13];
    const float* wg     = (const float*)d_in[14];
    const float* bg     = (const float*)d_in[15];
    const float* wf     = (const float*)d_in[16];
    const float* bf     = (const float*)d_in[17];
    const float* wxca   = (const float*)d_in[18];
    const float* wgate  = (const float*)d_in[20];
    const float* bgate  = (const float*)d_in[21];
    const float* wbb    = (const float*)d_in[22];
    float* out = (float*)d_out;

    node_v_kernel<<<NN/NVB, 512>>>(bbf, bbr, noise, xmask, X, wv, bv, w1, b1);
    row_kernel<<<NN, 256>>>(xmask);
    edge_kernel<<<NN*EPN/EPB, 256>>>(w1, w2, b2);
    agg_kernel<<<NN, 256>>>(X, bbr, noise, wo, bo, wg, bg, wf, bf,
                            wxca, wgate, bgate, wbb, out);
}